// round 1
// baseline (speedup 1.0000x reference)
#include <cuda_runtime.h>

#define D 256
#define MAXN 100000
#define BN_EPS 1e-5f

// ---- scratch (static device globals; no allocation allowed) ----
__device__ __align__(128) float g_h[MAXN * D];     // layer activations (layers >= 1)
__device__ __align__(128) float g_agg[MAXN * D];   // scatter target
__device__ __align__(128) float g_outb[MAXN * D];  // pre-BN output
__device__ float g_inv_out[MAXN];                  // deg_out^-1/2 (reused as counter)
__device__ float g_inv_in[MAXN];                   // deg_in^-1/2
__device__ float g_sum[D];
__device__ float g_sq[D];
__device__ float g_mean[D];
__device__ float g_istd[D];

// ---- helpers ----
__device__ __forceinline__ void red_add_v4(float* addr, float4 v) {
    asm volatile("red.global.add.v4.f32 [%0], {%1,%2,%3,%4};"
                 :: "l"(addr), "f"(v.x), "f"(v.y), "f"(v.z), "f"(v.w)
                 : "memory");
}

// ---- degree kernels ----
__global__ void zero_deg_kernel(int n) {
    for (int i = blockIdx.x * blockDim.x + threadIdx.x; i < n;
         i += gridDim.x * blockDim.x) {
        g_inv_out[i] = 0.0f;
        g_inv_in[i] = 0.0f;
    }
}

__global__ void deg_accum_kernel(const int* __restrict__ src,
                                 const int* __restrict__ dst, int e) {
    for (int i = blockIdx.x * blockDim.x + threadIdx.x; i < e;
         i += gridDim.x * blockDim.x) {
        atomicAdd(&g_inv_out[src[i]], 1.0f);
        atomicAdd(&g_inv_in[dst[i]], 1.0f);
    }
}

__global__ void deg_fin_kernel(int n) {
    for (int i = blockIdx.x * blockDim.x + threadIdx.x; i < n;
         i += gridDim.x * blockDim.x) {
        g_inv_out[i] = rsqrtf(fmaxf(g_inv_out[i], 1.0f));
        g_inv_in[i]  = rsqrtf(fmaxf(g_inv_in[i], 1.0f));
    }
}

// ---- zero agg + BN stats ----
__global__ void zero_agg_stats_kernel(int n) {
    int total4 = n * (D / 4);
    float4 z = make_float4(0.f, 0.f, 0.f, 0.f);
    float4* a4 = reinterpret_cast<float4*>(g_agg);
    for (int i = blockIdx.x * blockDim.x + threadIdx.x; i < total4;
         i += gridDim.x * blockDim.x)
        a4[i] = z;
    if (blockIdx.x == 0 && threadIdx.x < D) {
        g_sum[threadIdx.x] = 0.0f;
        g_sq[threadIdx.x] = 0.0f;
    }
}

// ---- scatter: agg[dst] += h[src] * inv_sqrt_out[src], feature-chunked for L2 ----
__global__ void scatter_kernel(const float* __restrict__ h,
                               const int* __restrict__ src,
                               const int* __restrict__ dst,
                               int e, int dimoff) {
    int lane = threadIdx.x & 31;
    int warp = (blockIdx.x * blockDim.x + threadIdx.x) >> 5;
    int nwarps = (gridDim.x * blockDim.x) >> 5;
    for (int ed = warp; ed < e; ed += nwarps) {
        int s = __ldg(&src[ed]);
        int d = __ldg(&dst[ed]);
        float sc = g_inv_out[s];
        float4 v = __ldg(reinterpret_cast<const float4*>(
            &h[(long)s * D + dimoff + lane * 4]));
        v.x *= sc; v.y *= sc; v.z *= sc; v.w *= sc;
        red_add_v4(&g_agg[(long)d * D + dimoff + lane * 4], v);
    }
}

// ---- fused GEMM: out = agg_scaled @ W + h @ Wl + h + b + bl, with BN stats ----
// A = [agg * inv_in | h]  (K = 512),  B = [W ; Wl]
__global__ void __launch_bounds__(256)
gemm_kernel(const float* __restrict__ h,
            const float* __restrict__ Wmat,   // W[l]   (256x256 row-major)
            const float* __restrict__ Wlmat,  // Wl[l]
            const float* __restrict__ bvec,   // b[l]
            const float* __restrict__ blvec,  // bl[l]
            int n) {
    __shared__ float As[16 * 132];
    __shared__ float Bs[16 * 132];
    __shared__ float s_sum[128];
    __shared__ float s_sq[128];

    int tid = threadIdx.x;
    int tx = tid & 15, ty = tid >> 4;
    int rowBase = blockIdx.x * 128;
    int colBase = blockIdx.y * 128;

    if (tid < 128) { s_sum[tid] = 0.0f; s_sq[tid] = 0.0f; }

    float acc[8][8];
#pragma unroll
    for (int i = 0; i < 8; i++)
#pragma unroll
        for (int j = 0; j < 8; j++) acc[i][j] = 0.0f;

    for (int kt = 0; kt < 32; kt++) {
#pragma unroll
        for (int t = 0; t < 2; t++) {
            int idx = tid + t * 256;
            // A tile: 128 rows x 16 k, stored transposed As[k][row]
            int r = idx >> 2, kq = idx & 3;
            int grow = rowBase + r;
            int kg = kt * 16 + kq * 4;
            float4 v = make_float4(0.f, 0.f, 0.f, 0.f);
            if (grow < n) {
                if (kg < 256) {
                    v = *reinterpret_cast<const float4*>(&g_agg[(long)grow * D + kg]);
                    float s = g_inv_in[grow];
                    v.x *= s; v.y *= s; v.z *= s; v.w *= s;
                } else {
                    v = *reinterpret_cast<const float4*>(&h[(long)grow * D + (kg - 256)]);
                }
            }
            As[(kq * 4 + 0) * 132 + r] = v.x;
            As[(kq * 4 + 1) * 132 + r] = v.y;
            As[(kq * 4 + 2) * 132 + r] = v.z;
            As[(kq * 4 + 3) * 132 + r] = v.w;
            // B tile: 16 k x 128 cols
            int k = idx >> 5, cq = idx & 31;
            int kg2 = kt * 16 + k;
            const float* bsrc = (kg2 < 256) ? (Wmat + (long)kg2 * D)
                                            : (Wlmat + (long)(kg2 - 256) * D);
            *reinterpret_cast<float4*>(&Bs[k * 132 + cq * 4]) =
                *reinterpret_cast<const float4*>(&bsrc[colBase + cq * 4]);
        }
        __syncthreads();
#pragma unroll
        for (int kk = 0; kk < 16; kk++) {
            float4 a0 = *reinterpret_cast<float4*>(&As[kk * 132 + ty * 4]);
            float4 a1 = *reinterpret_cast<float4*>(&As[kk * 132 + 64 + ty * 4]);
            float4 b0 = *reinterpret_cast<float4*>(&Bs[kk * 132 + tx * 4]);
            float4 b1 = *reinterpret_cast<float4*>(&Bs[kk * 132 + 64 + tx * 4]);
            float a[8] = {a0.x, a0.y, a0.z, a0.w, a1.x, a1.y, a1.z, a1.w};
            float b[8] = {b0.x, b0.y, b0.z, b0.w, b1.x, b1.y, b1.z, b1.w};
#pragma unroll
            for (int i = 0; i < 8; i++)
#pragma unroll
                for (int j = 0; j < 8; j++) acc[i][j] += a[i] * b[j];
        }
        __syncthreads();
    }

    // epilogue: + bias(b+bl) + residual h ; write out ; BN column partial sums
    float bias[8];
#pragma unroll
    for (int j = 0; j < 8; j++) {
        int c = colBase + ((j < 4) ? tx * 4 + j : 64 + tx * 4 + (j - 4));
        bias[j] = bvec[c] + blvec[c];
    }
    float csum[8], csq[8];
#pragma unroll
    for (int j = 0; j < 8; j++) { csum[j] = 0.0f; csq[j] = 0.0f; }

#pragma unroll
    for (int i = 0; i < 8; i++) {
        int r = rowBase + ((i < 4) ? ty * 4 + i : 64 + ty * 4 + (i - 4));
        if (r < n) {
            float4 h0 = *reinterpret_cast<const float4*>(&h[(long)r * D + colBase + tx * 4]);
            float4 h1 = *reinterpret_cast<const float4*>(&h[(long)r * D + colBase + 64 + tx * 4]);
            float hv[8] = {h0.x, h0.y, h0.z, h0.w, h1.x, h1.y, h1.z, h1.w};
            float4 o0, o1;
            float* o0p = &o0.x;
            float* o1p = &o1.x;
#pragma unroll
            for (int j = 0; j < 8; j++) {
                float v = acc[i][j] + bias[j] + hv[j];
                if (j < 4) o0p[j] = v; else o1p[j - 4] = v;
                csum[j] += v;
                csq[j] += v * v;
            }
            *reinterpret_cast<float4*>(&g_outb[(long)r * D + colBase + tx * 4]) = o0;
            *reinterpret_cast<float4*>(&g_outb[(long)r * D + colBase + 64 + tx * 4]) = o1;
        }
    }
#pragma unroll
    for (int j = 0; j < 8; j++) {
        int lc = (j < 4) ? tx * 4 + j : 64 + tx * 4 + (j - 4);
        atomicAdd(&s_sum[lc], csum[j]);
        atomicAdd(&s_sq[lc], csq[j]);
    }
    __syncthreads();
    if (tid < 128) {
        atomicAdd(&g_sum[colBase + tid], s_sum[tid]);
        atomicAdd(&g_sq[colBase + tid], s_sq[tid]);
    }
}

// ---- BN finalize ----
__global__ void bn_fin_kernel(int n) {
    int c = threadIdx.x;
    if (c < D) {
        float inv_n = 1.0f / (float)n;
        float mean = g_sum[c] * inv_n;
        float var = g_sq[c] * inv_n - mean * mean;
        g_mean[c] = mean;
        g_istd[c] = rsqrtf(var + BN_EPS);
    }
}

// ---- normalize + ReLU ----
__global__ void norm_relu_kernel(const float* __restrict__ gamma,
                                 const float* __restrict__ beta,
                                 float* __restrict__ dstp, int n) {
    int total4 = n * (D / 4);
    const float4* o4 = reinterpret_cast<const float4*>(g_outb);
    float4* d4 = reinterpret_cast<float4*>(dstp);
    for (int i = blockIdx.x * blockDim.x + threadIdx.x; i < total4;
         i += gridDim.x * blockDim.x) {
        int c = (i * 4) & (D - 1);
        float4 o = o4[i];
        float4 g = *reinterpret_cast<const float4*>(&gamma[c]);
        float4 be = *reinterpret_cast<const float4*>(&beta[c]);
        float4 m = *reinterpret_cast<const float4*>(&g_mean[c]);
        float4 s = *reinterpret_cast<const float4*>(&g_istd[c]);
        float4 r;
        r.x = fmaxf(g.x * (o.x - m.x) * s.x + be.x, 0.0f);
        r.y = fmaxf(g.y * (o.y - m.y) * s.y + be.y, 0.0f);
        r.z = fmaxf(g.z * (o.z - m.z) * s.z + be.z, 0.0f);
        r.w = fmaxf(g.w * (o.w - m.w) * s.w + be.w, 0.0f);
        d4[i] = r;
    }
}

// ---- host launcher ----
extern "C" void kernel_launch(void* const* d_in, const int* in_sizes, int n_in,
                              void* d_out, int out_size) {
    const float* x     = (const float*)d_in[0];
    const float* W     = (const float*)d_in[1];
    const float* b     = (const float*)d_in[2];
    const float* Wl    = (const float*)d_in[3];
    const float* bl    = (const float*)d_in[4];
    const float* gamma = (const float*)d_in[5];
    const float* beta  = (const float*)d_in[6];
    const int*   src   = (const int*)d_in[7];
    const int*   dst   = (const int*)d_in[8];

    int n = in_sizes[0] / D;
    int e = in_sizes[7];
    int nl = in_sizes[1] / (D * D);

    float* g_h_p = nullptr;
    cudaGetSymbolAddress((void**)&g_h_p, g_h);

    const int T = 256;
    int nblk = (n + T - 1) / T;

    // degrees (recomputed each call for determinism)
    zero_deg_kernel<<<nblk, T>>>(n);
    deg_accum_kernel<<<1184, T>>>(src, dst, e);
    deg_fin_kernel<<<nblk, T>>>(n);

    const float* hcur = x;
    for (int l = 0; l < nl; l++) {
        zero_agg_stats_kernel<<<1184, T>>>(n);
        scatter_kernel<<<2960, T>>>(hcur, src, dst, e, 0);
        scatter_kernel<<<2960, T>>>(hcur, src, dst, e, 128);
        dim3 gg((n + 127) / 128, 2);
        gemm_kernel<<<gg, T>>>(hcur, W + (long)l * D * D, Wl + (long)l * D * D,
                               b + l * D, bl + l * D, n);
        bn_fin_kernel<<<1, T>>>(n);
        float* dsth = (l == nl - 1) ? (float*)d_out : g_h_p;
        norm_relu_kernel<<<1184, T>>>(gamma + l * D, beta + l * D, dsth, n);
        hcur = g_h_p;
    }
}

// round 5
// speedup vs baseline: 1.2375x; 1.2375x over previous
#include <cuda_runtime.h>
#include <cuda_bf16.h>
#include <cstdint>

#define D 256
#define MAXN 100000
#define BN_EPS 1e-5f
#define LMAX 3

// ---- scratch (static device globals; no allocation allowed) ----
__device__ __align__(128) float g_h[MAXN * D];     // layer activations (layers >= 1)
__device__ __align__(128) float g_agg[MAXN * D];   // scatter target
__device__ __align__(128) float g_outb[MAXN * D];  // pre-BN output
__device__ float g_inv_out[MAXN];
__device__ float g_inv_in[MAXN];
__device__ float g_sum[D];
__device__ float g_sq[D];
__device__ float g_mean[D];
__device__ float g_istd[D];
// Weight images: B^T layout [L][n=256][k=512] bf16, hi and lo halves.
// Bop[n][k] = (k<256 ? W[l][k][n] : Wl[l][k-256][n] + I), split into hi+lo.
__device__ __align__(128) __nv_bfloat16 g_Bimg_hi[LMAX * 256 * 512];
__device__ __align__(128) __nv_bfloat16 g_Bimg_lo[LMAX * 256 * 512];

// ---- helpers ----
__device__ __forceinline__ void red_add_v4(float* addr, float4 v) {
    asm volatile("red.global.add.v4.f32 [%0], {%1,%2,%3,%4};"
                 :: "l"(addr), "f"(v.x), "f"(v.y), "f"(v.z), "f"(v.w)
                 : "memory");
}
__device__ __forceinline__ uint32_t cvta_s(const void* p) {
    uint32_t a;
    asm("{ .reg .u64 t; cvta.to.shared.u64 t, %1; cvt.u32.u64 %0, t; }"
        : "=r"(a) : "l"(p));
    return a;
}
__device__ __forceinline__ void ldm_x4(uint32_t& r0, uint32_t& r1,
                                       uint32_t& r2, uint32_t& r3, uint32_t a) {
    asm volatile("ldmatrix.sync.aligned.m8n8.x4.shared.b16 {%0,%1,%2,%3}, [%4];"
                 : "=r"(r0), "=r"(r1), "=r"(r2), "=r"(r3) : "r"(a));
}
__device__ __forceinline__ void mma_bf16(float* c, const uint32_t* a,
                                         uint32_t b0, uint32_t b1) {
    asm volatile(
        "mma.sync.aligned.m16n8k16.row.col.f32.bf16.bf16.f32 "
        "{%0,%1,%2,%3}, {%4,%5,%6,%7}, {%8,%9}, {%0,%1,%2,%3};"
        : "+f"(c[0]), "+f"(c[1]), "+f"(c[2]), "+f"(c[3])
        : "r"(a[0]), "r"(a[1]), "r"(a[2]), "r"(a[3]), "r"(b0), "r"(b1));
}
__device__ __forceinline__ uint32_t pack_bf2(__nv_bfloat16 a, __nv_bfloat16 b) {
    return (uint32_t)__bfloat16_as_ushort(a) | ((uint32_t)__bfloat16_as_ushort(b) << 16);
}
__device__ __forceinline__ void split_pair(float x, float y, uint32_t& hi, uint32_t& lo) {
    __nv_bfloat16 hx = __float2bfloat16(x);
    __nv_bfloat16 hy = __float2bfloat16(y);
    float rx = x - __bfloat162float(hx);
    float ry = y - __bfloat162float(hy);
    hi = pack_bf2(hx, hy);
    lo = pack_bf2(__float2bfloat16(rx), __float2bfloat16(ry));
}

// ---- degree kernels ----
__global__ void zero_deg_kernel(int n) {
    for (int i = blockIdx.x * blockDim.x + threadIdx.x; i < n;
         i += gridDim.x * blockDim.x) {
        g_inv_out[i] = 0.0f;
        g_inv_in[i] = 0.0f;
    }
}
__global__ void deg_accum_kernel(const int* __restrict__ src,
                                 const int* __restrict__ dst, int e) {
    for (int i = blockIdx.x * blockDim.x + threadIdx.x; i < e;
         i += gridDim.x * blockDim.x) {
        atomicAdd(&g_inv_out[src[i]], 1.0f);
        atomicAdd(&g_inv_in[dst[i]], 1.0f);
    }
}
__global__ void deg_fin_kernel(int n) {
    for (int i = blockIdx.x * blockDim.x + threadIdx.x; i < n;
         i += gridDim.x * blockDim.x) {
        g_inv_out[i] = rsqrtf(fmaxf(g_inv_out[i], 1.0f));
        g_inv_in[i]  = rsqrtf(fmaxf(g_inv_in[i], 1.0f));
    }
}

// ---- weight prep: B^T images, residual identity folded into Wl ----
__global__ void prep_B_kernel(const float* __restrict__ W,
                              const float* __restrict__ Wl, int nl) {
    int idx = blockIdx.x * blockDim.x + threadIdx.x;
    int total = nl * 256 * 512;
    if (idx >= total) return;
    int k = idx & 511;
    int nn = (idx >> 9) & 255;
    int l = idx >> 17;
    float w;
    if (k < 256) {
        w = W[((size_t)l * D + k) * D + nn];
    } else {
        w = Wl[((size_t)l * D + (k - 256)) * D + nn];
        if ((k - 256) == nn) w += 1.0f;   // residual h folded in
    }
    __nv_bfloat16 hi = __float2bfloat16(w);
    __nv_bfloat16 lo = __float2bfloat16(w - __bfloat162float(hi));
    g_Bimg_hi[idx] = hi;
    g_Bimg_lo[idx] = lo;
}

// ---- zero agg + BN stats ----
__global__ void zero_agg_stats_kernel(int n) {
    int total4 = n * (D / 4);
    float4 z = make_float4(0.f, 0.f, 0.f, 0.f);
    float4* a4 = reinterpret_cast<float4*>(g_agg);
    for (int i = blockIdx.x * blockDim.x + threadIdx.x; i < total4;
         i += gridDim.x * blockDim.x)
        a4[i] = z;
    if (blockIdx.x == 0 && threadIdx.x < D) {
        g_sum[threadIdx.x] = 0.0f;
        g_sq[threadIdx.x] = 0.0f;
    }
}

// ---- scatter: agg[dst] += h[src] * inv_sqrt_out[src], feature-chunked for L2 ----
__global__ void scatter_kernel(const float* __restrict__ h,
                               const int* __restrict__ src,
                               const int* __restrict__ dst,
                               int e, int dimoff) {
    int lane = threadIdx.x & 31;
    int warp = (blockIdx.x * blockDim.x + threadIdx.x) >> 5;
    int nwarps = (gridDim.x * blockDim.x) >> 5;
    for (int ed = warp; ed < e; ed += nwarps) {
        int s = __ldg(&src[ed]);
        int d = __ldg(&dst[ed]);
        float sc = g_inv_out[s];
        float4 v = __ldg(reinterpret_cast<const float4*>(
            &h[(long)s * D + dimoff + lane * 4]));
        v.x *= sc; v.y *= sc; v.z *= sc; v.w *= sc;
        red_add_v4(&g_agg[(long)d * D + dimoff + lane * 4], v);
    }
}

// ---- split-bf16 HMMA GEMM ----
// out[128 x 128 tile] = [agg*inv_in | h] (K=512) @ Bimg^T + b + bl (residual folded).
// 8 warps, warp tile 64x32 (m16n8k16), 3-product split emulation.
#define ASTRIDE 40   // bf16 elements per smem row (80B, conflict-free ldmatrix)
__global__ void __launch_bounds__(256)
gemm_mma_kernel(const float* __restrict__ h, int layer,
                const float* __restrict__ bvec, const float* __restrict__ blvec,
                int n) {
    __shared__ __nv_bfloat16 sAhi[128 * ASTRIDE];
    __shared__ __nv_bfloat16 sAlo[128 * ASTRIDE];
    __shared__ __nv_bfloat16 sBhi[128 * ASTRIDE];
    __shared__ __nv_bfloat16 sBlo[128 * ASTRIDE];

    int tid = threadIdx.x;
    int wid = tid >> 5, lane = tid & 31;
    int warp_m = wid >> 2;       // 0..1  (row offset *64)
    int warp_n = wid & 3;        // 0..3  (col offset *32)
    int rowBase = blockIdx.x * 128;
    int colBase = blockIdx.y * 128;

    uint32_t baseAhi = cvta_s(sAhi), baseAlo = cvta_s(sAlo);
    uint32_t baseBhi = cvta_s(sBhi), baseBlo = cvta_s(sBlo);

    const __nv_bfloat16* imgHi = g_Bimg_hi + (size_t)layer * 256 * 512;
    const __nv_bfloat16* imgLo = g_Bimg_lo + (size_t)layer * 256 * 512;

    float c[4][4][4];
#pragma unroll
    for (int i = 0; i < 4; i++)
#pragma unroll
        for (int j = 0; j < 4; j++)
#pragma unroll
            for (int q = 0; q < 4; q++) c[i][j][q] = 0.0f;

    // ldmatrix lane address components (shared across tiles)
    int lrow = lane & 15;
    int lhalf = lane >> 4;

    for (int kt = 0; kt < 16; kt++) {
        // ---- A tile: 128 rows x 32 k (fp32 -> split bf16) ----
#pragma unroll
        for (int i = 0; i < 4; i++) {
            int idx = tid + i * 256;          // 0..1023
            int row = idx >> 3, q = idx & 7;  // 8 float4 per row
            int grow = rowBase + row;
            float4 v = make_float4(0.f, 0.f, 0.f, 0.f);
            if (grow < n) {
                if (kt < 8) {
                    v = *reinterpret_cast<const float4*>(
                        &g_agg[(long)grow * D + kt * 32 + q * 4]);
                    float s = g_inv_in[grow];
                    v.x *= s; v.y *= s; v.z *= s; v.w *= s;
                } else {
                    v = *reinterpret_cast<const float4*>(
                        &h[(long)grow * D + (kt - 8) * 32 + q * 4]);
                }
            }
            uint32_t h0, l0, h1, l1;
            split_pair(v.x, v.y, h0, l0);
            split_pair(v.z, v.w, h1, l1);
            *reinterpret_cast<uint2*>(&sAhi[row * ASTRIDE + q * 4]) = make_uint2(h0, h1);
            *reinterpret_cast<uint2*>(&sAlo[row * ASTRIDE + q * 4]) = make_uint2(l0, l1);
        }
        // ---- B tile: 128 n-rows x 32 k (pre-split bf16 images) ----
#pragma unroll
        for (int i = 0; i < 4; i++) {
            int idx = tid + i * 256;          // 0..1023
            int half = idx >> 9;              // 0: hi, 1: lo
            int j = idx & 511;
            int nrow = j >> 2, q = j & 3;     // 4 x 16B per row
            const __nv_bfloat16* srcp = (half ? imgLo : imgHi)
                + ((size_t)(colBase + nrow) * 512 + kt * 32 + q * 8);
            uint4 val = *reinterpret_cast<const uint4*>(srcp);
            __nv_bfloat16* dstp = (half ? sBlo : sBhi) + nrow * ASTRIDE + q * 8;
            *reinterpret_cast<uint2*>(dstp) = make_uint2(val.x, val.y);
            *reinterpret_cast<uint2*>(dstp + 4) = make_uint2(val.z, val.w);
        }
        __syncthreads();

        // ---- compute: 2 k-steps of 16 ----
#pragma unroll
        for (int ks = 0; ks < 2; ks++) {
            uint32_t ahi[4][4], alo[4][4];
#pragma unroll
            for (int mt = 0; mt < 4; mt++) {
                uint32_t off = (uint32_t)((warp_m * 64 + mt * 16 + lrow) * 80
                                          + ks * 32 + lhalf * 16);
                ldm_x4(ahi[mt][0], ahi[mt][1], ahi[mt][2], ahi[mt][3], baseAhi + off);
                ldm_x4(alo[mt][0], alo[mt][1], alo[mt][2], alo[mt][3], baseAlo + off);
            }
            uint32_t bhi[4][2], blo[4][2];
#pragma unroll
            for (int np = 0; np < 2; np++) {
                uint32_t off = (uint32_t)((warp_n * 32 + np * 16 + lrow) * 80
                                          + ks * 32 + lhalf * 16);
                uint32_t q0, q1, q2, q3;
                ldm_x4(q0, q1, q2, q3, baseBhi + off);
                bhi[np * 2 + 0][0] = q0; bhi[np * 2 + 0][1] = q2;
                bhi[np * 2 + 1][0] = q1; bhi[np * 2 + 1][1] = q3;
                ldm_x4(q0, q1, q2, q3, baseBlo + off);
                blo[np * 2 + 0][0] = q0; blo[np * 2 + 0][1] = q2;
                blo[np * 2 + 1][0] = q1; blo[np * 2 + 1][1] = q3;
            }
#pragma unroll
            for (int mt = 0; mt < 4; mt++)
#pragma unroll
                for (int nt = 0; nt < 4; nt++) {
                    mma_bf16(c[mt][nt], ahi[mt], bhi[nt][0], bhi[nt][1]);
                    mma_bf16(c[mt][nt], ahi[mt], blo[nt][0], blo[nt][1]);
                    mma_bf16(c[mt][nt], alo[mt], bhi[nt][0], bhi[nt][1]);
                }
        }
        __syncthreads();
    }

    // ---- epilogue: + (b + bl), write g_outb ----
#pragma unroll
    for (int nt = 0; nt < 4; nt++) {
        int col = colBase + warp_n * 32 + nt * 8 + (lane & 3) * 2;
        float bx = bvec[col] + blvec[col];
        float by = bvec[col + 1] + blvec[col + 1];
#pragma unroll
        for (int mt = 0; mt < 4; mt++) {
            int r0 = rowBase + warp_m * 64 + mt * 16 + (lane >> 2);
            if (r0 < n) {
                float2 o0 = make_float2(c[mt][nt][0] + bx, c[mt][nt][1] + by);
                *reinterpret_cast<float2*>(&g_outb[(long)r0 * D + col]) = o0;
            }
            int r1 = r0 + 8;
            if (r1 < n) {
                float2 o1 = make_float2(c[mt][nt][2] + bx, c[mt][nt][3] + by);
                *reinterpret_cast<float2*>(&g_outb[(long)r1 * D + col]) = o1;
            }
        }
    }
}

// ---- BN column stats: each thread owns 4 fixed columns (stride % 64 == 0) ----
__global__ void bn_stats_kernel(int n) {
    int gid = blockIdx.x * blockDim.x + threadIdx.x;
    int stride = gridDim.x * blockDim.x;
    const float4* o4 = reinterpret_cast<const float4*>(g_outb);
    int total4 = n * (D / 4);
    float s0 = 0, s1 = 0, s2 = 0, s3 = 0, q0 = 0, q1 = 0, q2 = 0, q3 = 0;
    for (int i = gid; i < total4; i += stride) {
        float4 v = o4[i];
        s0 += v.x; q0 += v.x * v.x;
        s1 += v.y; q1 += v.y * v.y;
        s2 += v.z; q2 += v.z * v.z;
        s3 += v.w; q3 += v.w * v.w;
    }
    int cc = (gid & 63) * 4;
    atomicAdd(&g_sum[cc + 0], s0);
    atomicAdd(&g_sum[cc + 1], s1);
    atomicAdd(&g_sum[cc + 2], s2);
    atomicAdd(&g_sum[cc + 3], s3);
    atomicAdd(&g_sq[cc + 0], q0);
    atomicAdd(&g_sq[cc + 1], q1);
    atomicAdd(&g_sq[cc + 2], q2);
    atomicAdd(&g_sq[cc + 3], q3);
}

// ---- BN finalize ----
__global__ void bn_fin_kernel(int n) {
    int c = threadIdx.x;
    if (c < D) {
        float inv_n = 1.0f / (float)n;
        float mean = g_sum[c] * inv_n;
        float var = g_sq[c] * inv_n - mean * mean;
        g_mean[c] = mean;
        g_istd[c] = rsqrtf(var + BN_EPS);
    }
}

// ---- normalize + ReLU ----
__global__ void norm_relu_kernel(const float* __restrict__ gamma,
                                 const float* __restrict__ beta,
                                 float* __restrict__ dstp, int n) {
    int total4 = n * (D / 4);
    const float4* o4 = reinterpret_cast<const float4*>(g_outb);
    float4* d4 = reinterpret_cast<float4*>(dstp);
    for (int i = blockIdx.x * blockDim.x + threadIdx.x; i < total4;
         i += gridDim.x * blockDim.x) {
        int c = (i * 4) & (D - 1);
        float4 o = o4[i];
        float4 g = *reinterpret_cast<const float4*>(&gamma[c]);
        float4 be = *reinterpret_cast<const float4*>(&beta[c]);
        float4 m = *reinterpret_cast<const float4*>(&g_mean[c]);
        float4 s = *reinterpret_cast<const float4*>(&g_istd[c]);
        float4 r;
        r.x = fmaxf(g.x * (o.x - m.x) * s.x + be.x, 0.0f);
        r.y = fmaxf(g.y * (o.y - m.y) * s.y + be.y, 0.0f);
        r.z = fmaxf(g.z * (o.z - m.z) * s.z + be.z, 0.0f);
        r.w = fmaxf(g.w * (o.w - m.w) * s.w + be.w, 0.0f);
        d4[i] = r;
    }
}

// ---- host launcher ----
extern "C" void kernel_launch(void* const* d_in, const int* in_sizes, int n_in,
                              void* d_out, int out_size) {
    const float* x     = (const float*)d_in[0];
    const float* W     = (const float*)d_in[1];
    const float* b     = (const float*)d_in[2];
    const float* Wl    = (const float*)d_in[3];
    const float* bl    = (const float*)d_in[4];
    const float* gamma = (const float*)d_in[5];
    const float* beta  = (const float*)d_in[6];
    const int*   src   = (const int*)d_in[7];
    const int*   dst   = (const int*)d_in[8];

    int n = in_sizes[0] / D;
    int e = in_sizes[7];
    int nl = in_sizes[1] / (D * D);

    float* g_h_p = nullptr;
    cudaGetSymbolAddress((void**)&g_h_p, g_h);

    const int T = 256;
    int nblk = (n + T - 1) / T;

    // degrees
    zero_deg_kernel<<<nblk, T>>>(n);
    deg_accum_kernel<<<1184, T>>>(src, dst, e);
    deg_fin_kernel<<<nblk, T>>>(n);

    // weight prep (all layers)
    int preptasks = nl * 256 * 512;
    prep_B_kernel<<<(preptasks + T - 1) / T, T>>>(W, Wl, nl);

    const float* hcur = x;
    for (int l = 0; l < nl; l++) {
        zero_agg_stats_kernel<<<1184, T>>>(n);
        scatter_kernel<<<2960, T>>>(hcur, src, dst, e, 0);
        scatter_kernel<<<2960, T>>>(hcur, src, dst, e, 128);
        dim3 gg((n + 127) / 128, 2);
        gemm_mma_kernel<<<gg, T>>>(hcur, l, b + l * D, bl + l * D, n);
        bn_stats_kernel<<<592, T>>>(n);
        bn_fin_kernel<<<1, T>>>(n);
        float* dsth = (l == nl - 1) ? (float*)d_out : g_h_p;
        norm_relu_kernel<<<1184, T>>>(gamma + l * D, beta + l * D, dsth, n);
        hcur = g_h_p;
    }
}

// round 6
// speedup vs baseline: 1.9691x; 1.5912x over previous
#include <cuda_runtime.h>
#include <cuda_bf16.h>
#include <cstdint>

#define D 256
#define MAXN 100000
#define MAXE 3200000
#define BN_EPS 1e-5f
#define LMAX 3

// ---- scratch (static device globals; no allocation allowed) ----
__device__ __align__(128) float g_h[MAXN * D];
__device__ __align__(128) float g_agg[MAXN * D];
__device__ __align__(128) float g_outb[MAXN * D];
__device__ float g_inv_out[MAXN];
__device__ float g_inv_in[MAXN];
__device__ int   g_degi_out[MAXN];
__device__ int   g_degi_in[MAXN];
__device__ int   g_rowp[MAXN + 1];
__device__ int   g_cursor[MAXN];
__device__ int   g_esrc[MAXE];
__device__ float g_sum[D];
__device__ float g_sq[D];
__device__ float g_mean[D];
__device__ float g_istd[D];
// Weight images: B^T layout [L][n=256][k=512] bf16, hi and lo halves.
__device__ __align__(128) __nv_bfloat16 g_Bimg_hi[LMAX * 256 * 512];
__device__ __align__(128) __nv_bfloat16 g_Bimg_lo[LMAX * 256 * 512];

// ---- helpers ----
__device__ __forceinline__ uint32_t cvta_s(const void* p) {
    uint32_t a;
    asm("{ .reg .u64 t; cvta.to.shared.u64 t, %1; cvt.u32.u64 %0, t; }"
        : "=r"(a) : "l"(p));
    return a;
}
__device__ __forceinline__ void ldm_x4(uint32_t& r0, uint32_t& r1,
                                       uint32_t& r2, uint32_t& r3, uint32_t a) {
    asm volatile("ldmatrix.sync.aligned.m8n8.x4.shared.b16 {%0,%1,%2,%3}, [%4];"
                 : "=r"(r0), "=r"(r1), "=r"(r2), "=r"(r3) : "r"(a));
}
__device__ __forceinline__ void mma_bf16(float* c, const uint32_t* a,
                                         uint32_t b0, uint32_t b1) {
    asm volatile(
        "mma.sync.aligned.m16n8k16.row.col.f32.bf16.bf16.f32 "
        "{%0,%1,%2,%3}, {%4,%5,%6,%7}, {%8,%9}, {%0,%1,%2,%3};"
        : "+f"(c[0]), "+f"(c[1]), "+f"(c[2]), "+f"(c[3])
        : "r"(a[0]), "r"(a[1]), "r"(a[2]), "r"(a[3]), "r"(b0), "r"(b1));
}
__device__ __forceinline__ uint32_t pack_bf2(__nv_bfloat16 a, __nv_bfloat16 b) {
    return (uint32_t)__bfloat16_as_ushort(a) | ((uint32_t)__bfloat16_as_ushort(b) << 16);
}
__device__ __forceinline__ void split_pair(float x, float y, uint32_t& hi, uint32_t& lo) {
    __nv_bfloat16 hx = __float2bfloat16(x);
    __nv_bfloat16 hy = __float2bfloat16(y);
    float rx = x - __bfloat162float(hx);
    float ry = y - __bfloat162float(hy);
    hi = pack_bf2(hx, hy);
    lo = pack_bf2(__float2bfloat16(rx), __float2bfloat16(ry));
}

// ---- degree / CSR build ----
__global__ void zero_deg_kernel(int n) {
    for (int i = blockIdx.x * blockDim.x + threadIdx.x; i < n;
         i += gridDim.x * blockDim.x) {
        g_degi_out[i] = 0;
        g_degi_in[i] = 0;
    }
}
__global__ void deg_accum_kernel(const int* __restrict__ src,
                                 const int* __restrict__ dst, int e) {
    for (int i = blockIdx.x * blockDim.x + threadIdx.x; i < e;
         i += gridDim.x * blockDim.x) {
        atomicAdd(&g_degi_out[src[i]], 1);
        atomicAdd(&g_degi_in[dst[i]], 1);
    }
}
__global__ void deg_fin_kernel(int n) {
    for (int i = blockIdx.x * blockDim.x + threadIdx.x; i < n;
         i += gridDim.x * blockDim.x) {
        g_inv_out[i] = rsqrtf(fmaxf((float)g_degi_out[i], 1.0f));
        g_inv_in[i]  = rsqrtf(fmaxf((float)g_degi_in[i], 1.0f));
    }
}
// single-block exclusive scan of deg_in -> rowp (+ cursor copy)
__global__ void __launch_bounds__(1024)
scan_kernel(int n) {
    __shared__ int warp_sums[32];
    __shared__ int s_running;
    int lane = threadIdx.x & 31, w = threadIdx.x >> 5;
    if (threadIdx.x == 0) s_running = 0;
    __syncthreads();
    for (int base = 0; base < n; base += 1024) {
        int i = base + (int)threadIdx.x;
        int c = (i < n) ? g_degi_in[i] : 0;
        int v = c;
#pragma unroll
        for (int o = 1; o < 32; o <<= 1) {
            int t = __shfl_up_sync(0xFFFFFFFFu, v, o);
            if (lane >= o) v += t;
        }
        if (lane == 31) warp_sums[w] = v;
        __syncthreads();
        if (w == 0) {
            int s = warp_sums[lane];
#pragma unroll
            for (int o = 1; o < 32; o <<= 1) {
                int t = __shfl_up_sync(0xFFFFFFFFu, s, o);
                if (lane >= o) s += t;
            }
            warp_sums[lane] = s;
        }
        __syncthreads();
        int run = s_running;
        int excl = v - c + (w > 0 ? warp_sums[w - 1] : 0);
        if (i < n) {
            g_rowp[i] = run + excl;
            g_cursor[i] = run + excl;
        }
        __syncthreads();
        if (threadIdx.x == 1023) s_running = run + warp_sums[31];
        __syncthreads();
    }
    if (threadIdx.x == 0) g_rowp[n] = s_running;
}
__global__ void bucket_kernel(const int* __restrict__ src,
                              const int* __restrict__ dst, int e) {
    for (int i = blockIdx.x * blockDim.x + threadIdx.x; i < e;
         i += gridDim.x * blockDim.x) {
        int pos = atomicAdd(&g_cursor[dst[i]], 1);
        g_esrc[pos] = src[i];
    }
}

// ---- weight prep: B^T images, residual identity folded into Wl ----
__global__ void prep_B_kernel(const float* __restrict__ W,
                              const float* __restrict__ Wl, int nl) {
    int idx = blockIdx.x * blockDim.x + threadIdx.x;
    int total = nl * 256 * 512;
    if (idx >= total) return;
    int k = idx & 511;
    int nn = (idx >> 9) & 255;
    int l = idx >> 17;
    float w;
    if (k < 256) {
        w = W[((size_t)l * D + k) * D + nn];
    } else {
        w = Wl[((size_t)l * D + (k - 256)) * D + nn];
        if ((k - 256) == nn) w += 1.0f;   // residual h folded in
    }
    __nv_bfloat16 hi = __float2bfloat16(w);
    __nv_bfloat16 lo = __float2bfloat16(w - __bfloat162float(hi));
    g_Bimg_hi[idx] = hi;
    g_Bimg_lo[idx] = lo;
}

__global__ void zero_stats_kernel() {
    if (threadIdx.x < D) {
        g_sum[threadIdx.x] = 0.0f;
        g_sq[threadIdx.x] = 0.0f;
    }
}

// ---- gather aggregate: agg[v] = inv_in[v] * sum_{u in N_in(v)} h[u]*inv_out[u] ----
// one warp per node per 128-feature chunk
__global__ void __launch_bounds__(256)
gather_kernel(const float* __restrict__ h, int n, int dimoff) {
    int node = (blockIdx.x * blockDim.x + threadIdx.x) >> 5;
    if (node >= n) return;
    int lane = threadIdx.x & 31;
    int e0 = __ldg(&g_rowp[node]);
    int e1 = __ldg(&g_rowp[node + 1]);
    float ax = 0.f, ay = 0.f, az = 0.f, aw = 0.f;
    int ed = e0;
    for (; ed + 2 <= e1; ed += 2) {
        int s0 = __ldg(&g_esrc[ed]);
        int s1 = __ldg(&g_esrc[ed + 1]);
        float c0 = __ldg(&g_inv_out[s0]);
        float c1 = __ldg(&g_inv_out[s1]);
        float4 v0 = __ldg(reinterpret_cast<const float4*>(
            &h[(long)s0 * D + dimoff + lane * 4]));
        float4 v1 = __ldg(reinterpret_cast<const float4*>(
            &h[(long)s1 * D + dimoff + lane * 4]));
        ax += v0.x * c0 + v1.x * c1;
        ay += v0.y * c0 + v1.y * c1;
        az += v0.z * c0 + v1.z * c1;
        aw += v0.w * c0 + v1.w * c1;
    }
    if (ed < e1) {
        int s0 = __ldg(&g_esrc[ed]);
        float c0 = __ldg(&g_inv_out[s0]);
        float4 v0 = __ldg(reinterpret_cast<const float4*>(
            &h[(long)s0 * D + dimoff + lane * 4]));
        ax += v0.x * c0; ay += v0.y * c0; az += v0.z * c0; aw += v0.w * c0;
    }
    float si = g_inv_in[node];
    float4 o = make_float4(ax * si, ay * si, az * si, aw * si);
    *reinterpret_cast<float4*>(&g_agg[(long)node * D + dimoff + lane * 4]) = o;
}

// ---- split-bf16 HMMA GEMM ----
// out[128 x 128 tile] = [agg | h] (K=512) @ Bimg^T + b + bl (residual folded).
#define ASTRIDE 40
__global__ void __launch_bounds__(256)
gemm_mma_kernel(const float* __restrict__ h, int layer,
                const float* __restrict__ bvec, const float* __restrict__ blvec,
                int n) {
    __shared__ __nv_bfloat16 sAhi[128 * ASTRIDE];
    __shared__ __nv_bfloat16 sAlo[128 * ASTRIDE];
    __shared__ __nv_bfloat16 sBhi[128 * ASTRIDE];
    __shared__ __nv_bfloat16 sBlo[128 * ASTRIDE];

    int tid = threadIdx.x;
    int wid = tid >> 5, lane = tid & 31;
    int warp_m = wid >> 2;
    int warp_n = wid & 3;
    int rowBase = blockIdx.x * 128;
    int colBase = blockIdx.y * 128;

    uint32_t baseAhi = cvta_s(sAhi), baseAlo = cvta_s(sAlo);
    uint32_t baseBhi = cvta_s(sBhi), baseBlo = cvta_s(sBlo);

    const __nv_bfloat16* imgHi = g_Bimg_hi + (size_t)layer * 256 * 512;
    const __nv_bfloat16* imgLo = g_Bimg_lo + (size_t)layer * 256 * 512;

    float c[4][4][4];
#pragma unroll
    for (int i = 0; i < 4; i++)
#pragma unroll
        for (int j = 0; j < 4; j++)
#pragma unroll
            for (int q = 0; q < 4; q++) c[i][j][q] = 0.0f;

    int lrow = lane & 15;
    int lhalf = lane >> 4;

    for (int kt = 0; kt < 16; kt++) {
#pragma unroll
        for (int i = 0; i < 4; i++) {
            int idx = tid + i * 256;
            int row = idx >> 3, q = idx & 7;
            int grow = rowBase + row;
            float4 v = make_float4(0.f, 0.f, 0.f, 0.f);
            if (grow < n) {
                if (kt < 8) {
                    v = *reinterpret_cast<const float4*>(
                        &g_agg[(long)grow * D + kt * 32 + q * 4]);
                } else {
                    v = *reinterpret_cast<const float4*>(
                        &h[(long)grow * D + (kt - 8) * 32 + q * 4]);
                }
            }
            uint32_t h0, l0, h1, l1;
            split_pair(v.x, v.y, h0, l0);
            split_pair(v.z, v.w, h1, l1);
            *reinterpret_cast<uint2*>(&sAhi[row * ASTRIDE + q * 4]) = make_uint2(h0, h1);
            *reinterpret_cast<uint2*>(&sAlo[row * ASTRIDE + q * 4]) = make_uint2(l0, l1);
        }
#pragma unroll
        for (int i = 0; i < 4; i++) {
            int idx = tid + i * 256;
            int half = idx >> 9;
            int j = idx & 511;
            int nrow = j >> 2, q = j & 3;
            const __nv_bfloat16* srcp = (half ? imgLo : imgHi)
                + ((size_t)(colBase + nrow) * 512 + kt * 32 + q * 8);
            uint4 val = *reinterpret_cast<const uint4*>(srcp);
            __nv_bfloat16* dstp = (half ? sBlo : sBhi) + nrow * ASTRIDE + q * 8;
            *reinterpret_cast<uint2*>(dstp) = make_uint2(val.x, val.y);
            *reinterpret_cast<uint2*>(dstp + 4) = make_uint2(val.z, val.w);
        }
        __syncthreads();

#pragma unroll
        for (int ks = 0; ks < 2; ks++) {
            uint32_t ahi[4][4], alo[4][4];
#pragma unroll
            for (int mt = 0; mt < 4; mt++) {
                uint32_t off = (uint32_t)((warp_m * 64 + mt * 16 + lrow) * 80
                                          + ks * 32 + lhalf * 16);
                ldm_x4(ahi[mt][0], ahi[mt][1], ahi[mt][2], ahi[mt][3], baseAhi + off);
                ldm_x4(alo[mt][0], alo[mt][1], alo[mt][2], alo[mt][3], baseAlo + off);
            }
            uint32_t bhi[4][2], blo[4][2];
#pragma unroll
            for (int np = 0; np < 2; np++) {
                uint32_t off = (uint32_t)((warp_n * 32 + np * 16 + lrow) * 80
                                          + ks * 32 + lhalf * 16);
                uint32_t q0, q1, q2, q3;
                ldm_x4(q0, q1, q2, q3, baseBhi + off);
                bhi[np * 2 + 0][0] = q0; bhi[np * 2 + 0][1] = q2;
                bhi[np * 2 + 1][0] = q1; bhi[np * 2 + 1][1] = q3;
                ldm_x4(q0, q1, q2, q3, baseBlo + off);
                blo[np * 2 + 0][0] = q0; blo[np * 2 + 0][1] = q2;
                blo[np * 2 + 1][0] = q1; blo[np * 2 + 1][1] = q3;
            }
#pragma unroll
            for (int mt = 0; mt < 4; mt++)
#pragma unroll
                for (int nt = 0; nt < 4; nt++) {
                    mma_bf16(c[mt][nt], ahi[mt], bhi[nt][0], bhi[nt][1]);
                    mma_bf16(c[mt][nt], ahi[mt], blo[nt][0], blo[nt][1]);
                    mma_bf16(c[mt][nt], alo[mt], bhi[nt][0], bhi[nt][1]);
                }
        }
        __syncthreads();
    }

#pragma unroll
    for (int nt = 0; nt < 4; nt++) {
        int col = colBase + warp_n * 32 + nt * 8 + (lane & 3) * 2;
        float bx = bvec[col] + blvec[col];
        float by = bvec[col + 1] + blvec[col + 1];
#pragma unroll
        for (int mt = 0; mt < 4; mt++) {
            int r0 = rowBase + warp_m * 64 + mt * 16 + (lane >> 2);
            if (r0 < n) {
                float2 o0 = make_float2(c[mt][nt][0] + bx, c[mt][nt][1] + by);
                *reinterpret_cast<float2*>(&g_outb[(long)r0 * D + col]) = o0;
            }
            int r1 = r0 + 8;
            if (r1 < n) {
                float2 o1 = make_float2(c[mt][nt][2] + bx, c[mt][nt][3] + by);
                *reinterpret_cast<float2*>(&g_outb[(long)r1 * D + col]) = o1;
            }
        }
    }
}

// ---- BN column stats ----
__global__ void bn_stats_kernel(int n) {
    int gid = blockIdx.x * blockDim.x + threadIdx.x;
    int stride = gridDim.x * blockDim.x;
    const float4* o4 = reinterpret_cast<const float4*>(g_outb);
    int total4 = n * (D / 4);
    float s0 = 0, s1 = 0, s2 = 0, s3 = 0, q0 = 0, q1 = 0, q2 = 0, q3 = 0;
    for (int i = gid; i < total4; i += stride) {
        float4 v = o4[i];
        s0 += v.x; q0 += v.x * v.x;
        s1 += v.y; q1 += v.y * v.y;
        s2 += v.z; q2 += v.z * v.z;
        s3 += v.w; q3 += v.w * v.w;
    }
    int cc = (gid & 63) * 4;
    atomicAdd(&g_sum[cc + 0], s0);
    atomicAdd(&g_sum[cc + 1], s1);
    atomicAdd(&g_sum[cc + 2], s2);
    atomicAdd(&g_sum[cc + 3], s3);
    atomicAdd(&g_sq[cc + 0], q0);
    atomicAdd(&g_sq[cc + 1], q1);
    atomicAdd(&g_sq[cc + 2], q2);
    atomicAdd(&g_sq[cc + 3], q3);
}

// ---- BN finalize ----
__global__ void bn_fin_kernel(int n) {
    int c = threadIdx.x;
    if (c < D) {
        float inv_n = 1.0f / (float)n;
        float mean = g_sum[c] * inv_n;
        float var = g_sq[c] * inv_n - mean * mean;
        g_mean[c] = mean;
        g_istd[c] = rsqrtf(var + BN_EPS);
    }
}

// ---- normalize + ReLU ----
__global__ void norm_relu_kernel(const float* __restrict__ gamma,
                                 const float* __restrict__ beta,
                                 float* __restrict__ dstp, int n) {
    int total4 = n * (D / 4);
    const float4* o4 = reinterpret_cast<const float4*>(g_outb);
    float4* d4 = reinterpret_cast<float4*>(dstp);
    for (int i = blockIdx.x * blockDim.x + threadIdx.x; i < total4;
         i += gridDim.x * blockDim.x) {
        int c = (i * 4) & (D - 1);
        float4 o = o4[i];
        float4 g = *reinterpret_cast<const float4*>(&gamma[c]);
        float4 be = *reinterpret_cast<const float4*>(&beta[c]);
        float4 m = *reinterpret_cast<const float4*>(&g_mean[c]);
        float4 s = *reinterpret_cast<const float4*>(&g_istd[c]);
        float4 r;
        r.x = fmaxf(g.x * (o.x - m.x) * s.x + be.x, 0.0f);
        r.y = fmaxf(g.y * (o.y - m.y) * s.y + be.y, 0.0f);
        r.z = fmaxf(g.z * (o.z - m.z) * s.z + be.z, 0.0f);
        r.w = fmaxf(g.w * (o.w - m.w) * s.w + be.w, 0.0f);
        d4[i] = r;
    }
}

// ---- host launcher ----
extern "C" void kernel_launch(void* const* d_in, const int* in_sizes, int n_in,
                              void* d_out, int out_size) {
    const float* x     = (const float*)d_in[0];
    const float* W     = (const float*)d_in[1];
    const float* b     = (const float*)d_in[2];
    const float* Wl    = (const float*)d_in[3];
    const float* bl    = (const float*)d_in[4];
    const float* gamma = (const float*)d_in[5];
    const float* beta  = (const float*)d_in[6];
    const int*   src   = (const int*)d_in[7];
    const int*   dst   = (const int*)d_in[8];

    int n = in_sizes[0] / D;
    int e = in_sizes[7];
    int nl = in_sizes[1] / (D * D);

    float* g_h_p = nullptr;
    cudaGetSymbolAddress((void**)&g_h_p, g_h);

    const int T = 256;
    int nblk = (n + T - 1) / T;

    // degrees + CSR (once; graph static across layers)
    zero_deg_kernel<<<nblk, T>>>(n);
    deg_accum_kernel<<<1184, T>>>(src, dst, e);
    deg_fin_kernel<<<nblk, T>>>(n);
    scan_kernel<<<1, 1024>>>(n);
    bucket_kernel<<<1184, T>>>(src, dst, e);

    // weight prep (all layers)
    int preptasks = nl * 256 * 512;
    prep_B_kernel<<<(preptasks + T - 1) / T, T>>>(W, Wl, nl);

    int gather_blocks = (n * 32 + T - 1) / T;   // one warp per node
    const float* hcur = x;
    for (int l = 0; l < nl; l++) {
        zero_stats_kernel<<<1, T>>>();
        gather_kernel<<<gather_blocks, T>>>(hcur, n, 0);
        gather_kernel<<<gather_blocks, T>>>(hcur, n, 128);
        dim3 gg((n + 127) / 128, 2);
        gemm_mma_kernel<<<gg, T>>>(hcur, l, b + l * D, bl + l * D, n);
        bn_stats_kernel<<<592, T>>>(n);
        bn_fin_kernel<<<1, T>>>(n);
        float* dsth = (l == nl - 1) ? (float*)d_out : g_h_p;
        norm_relu_kernel<<<1184, T>>>(gamma + l * D, beta + l * D, dsth, n);
        hcur = g_h_p;
    }
}

// round 7
// speedup vs baseline: 2.2122x; 1.1235x over previous
#include <cuda_runtime.h>
#include <cuda_bf16.h>
#include <cstdint>

#define D 256
#define MAXN 100000
#define MAXE 3200000
#define BN_EPS 1e-5f
#define LMAX 3
#define SCAN_CHUNK 4096

// ---- scratch (static device globals; no allocation allowed) ----
__device__ __align__(128) float g_h[MAXN * D];
__device__ __align__(128) float g_agg[MAXN * D];
__device__ __align__(128) float g_outb[MAXN * D];
__device__ float g_inv_out[MAXN];
__device__ float g_inv_in[MAXN];
__device__ int   g_degi_out[MAXN];
__device__ int   g_degi_in[MAXN];
__device__ int   g_rowp[MAXN + 1];
__device__ int   g_cursor[MAXN];
__device__ int   g_esrc[MAXE];
__device__ int   g_bsum[128];
__device__ int   g_boff[128];
__device__ float g_sum[D];
__device__ float g_sq[D];
__device__ float g_mean[D];
__device__ float g_istd[D];
// Weight images: B^T layout [L][n=256][k=512] bf16, hi and lo halves.
__device__ __align__(128) __nv_bfloat16 g_Bimg_hi[LMAX * 256 * 512];
__device__ __align__(128) __nv_bfloat16 g_Bimg_lo[LMAX * 256 * 512];

// ---- helpers ----
__device__ __forceinline__ uint32_t cvta_s(const void* p) {
    uint32_t a;
    asm("{ .reg .u64 t; cvta.to.shared.u64 t, %1; cvt.u32.u64 %0, t; }"
        : "=r"(a) : "l"(p));
    return a;
}
__device__ __forceinline__ void ldm_x4(uint32_t& r0, uint32_t& r1,
                                       uint32_t& r2, uint32_t& r3, uint32_t a) {
    asm volatile("ldmatrix.sync.aligned.m8n8.x4.shared.b16 {%0,%1,%2,%3}, [%4];"
                 : "=r"(r0), "=r"(r1), "=r"(r2), "=r"(r3) : "r"(a));
}
__device__ __forceinline__ void mma_bf16(float* c, const uint32_t* a,
                                         uint32_t b0, uint32_t b1) {
    asm volatile(
        "mma.sync.aligned.m16n8k16.row.col.f32.bf16.bf16.f32 "
        "{%0,%1,%2,%3}, {%4,%5,%6,%7}, {%8,%9}, {%0,%1,%2,%3};"
        : "+f"(c[0]), "+f"(c[1]), "+f"(c[2]), "+f"(c[3])
        : "r"(a[0]), "r"(a[1]), "r"(a[2]), "r"(a[3]), "r"(b0), "r"(b1));
}
__device__ __forceinline__ uint32_t pack_bf2(__nv_bfloat16 a, __nv_bfloat16 b) {
    return (uint32_t)__bfloat16_as_ushort(a) | ((uint32_t)__bfloat16_as_ushort(b) << 16);
}
__device__ __forceinline__ void split_pair(float x, float y, uint32_t& hi, uint32_t& lo) {
    __nv_bfloat16 hx = __float2bfloat16(x);
    __nv_bfloat16 hy = __float2bfloat16(y);
    float rx = x - __bfloat162float(hx);
    float ry = y - __bfloat162float(hy);
    hi = pack_bf2(hx, hy);
    lo = pack_bf2(__float2bfloat16(rx), __float2bfloat16(ry));
}

// ---- degree / CSR build ----
__global__ void zero_deg_kernel(int n) {
    for (int i = blockIdx.x * blockDim.x + threadIdx.x; i < n;
         i += gridDim.x * blockDim.x) {
        g_degi_out[i] = 0;
        g_degi_in[i] = 0;
    }
}
__global__ void deg_accum_kernel(const int* __restrict__ src,
                                 const int* __restrict__ dst, int e) {
    for (int i = blockIdx.x * blockDim.x + threadIdx.x; i < e;
         i += gridDim.x * blockDim.x) {
        atomicAdd(&g_degi_out[src[i]], 1);
        atomicAdd(&g_degi_in[dst[i]], 1);
    }
}
__global__ void deg_fin_kernel(int n) {
    for (int i = blockIdx.x * blockDim.x + threadIdx.x; i < n;
         i += gridDim.x * blockDim.x) {
        g_inv_out[i] = rsqrtf(fmaxf((float)g_degi_out[i], 1.0f));
        g_inv_in[i]  = rsqrtf(fmaxf((float)g_degi_in[i], 1.0f));
    }
}
// multi-block scan, phase 1: block-local exclusive scan of deg_in over 4096 elems
__global__ void __launch_bounds__(1024)
scan1_kernel(int n) {
    __shared__ int wsum[32];
    int t = threadIdx.x;
    int lane = t & 31, w = t >> 5;
    int base = blockIdx.x * SCAN_CHUNK + t * 4;
    int v0 = (base + 0 < n) ? g_degi_in[base + 0] : 0;
    int v1 = (base + 1 < n) ? g_degi_in[base + 1] : 0;
    int v2 = (base + 2 < n) ? g_degi_in[base + 2] : 0;
    int v3 = (base + 3 < n) ? g_degi_in[base + 3] : 0;
    int s = v0 + v1 + v2 + v3;
    int inc = s;
#pragma unroll
    for (int o = 1; o < 32; o <<= 1) {
        int u = __shfl_up_sync(0xFFFFFFFFu, inc, o);
        if (lane >= o) inc += u;
    }
    if (lane == 31) wsum[w] = inc;
    __syncthreads();
    if (w == 0) {
        int ws = wsum[lane];
#pragma unroll
        for (int o = 1; o < 32; o <<= 1) {
            int u = __shfl_up_sync(0xFFFFFFFFu, ws, o);
            if (lane >= o) ws += u;
        }
        wsum[lane] = ws;
    }
    __syncthreads();
    int excl = inc - s + (w > 0 ? wsum[w - 1] : 0);
    if (base + 0 < n) g_rowp[base + 0] = excl;
    if (base + 1 < n) g_rowp[base + 1] = excl + v0;
    if (base + 2 < n) g_rowp[base + 2] = excl + v0 + v1;
    if (base + 3 < n) g_rowp[base + 3] = excl + v0 + v1 + v2;
    if (t == 0) g_bsum[blockIdx.x] = 0;   // ensure defined
    __syncthreads();
    if (t == 1023) g_bsum[blockIdx.x] = wsum[31];
}
// phase 2: tiny serial scan of block sums (nblk <= 128)
__global__ void scan2_kernel(int nblk, int n) {
    if (threadIdx.x == 0) {
        int run = 0;
        for (int b = 0; b < nblk; b++) {
            g_boff[b] = run;
            run += g_bsum[b];
        }
        g_rowp[n] = run;
    }
}
// phase 3: add block offsets; copy to cursor
__global__ void scan3_kernel(int n) {
    for (int i = blockIdx.x * blockDim.x + threadIdx.x; i < n;
         i += gridDim.x * blockDim.x) {
        int v = g_rowp[i] + g_boff[i / SCAN_CHUNK];
        g_rowp[i] = v;
        g_cursor[i] = v;
    }
}
__global__ void bucket_kernel(const int* __restrict__ src,
                              const int* __restrict__ dst, int e) {
    for (int i = blockIdx.x * blockDim.x + threadIdx.x; i < e;
         i += gridDim.x * blockDim.x) {
        int pos = atomicAdd(&g_cursor[dst[i]], 1);
        g_esrc[pos] = src[i];
    }
}

// ---- weight prep: B^T images, residual identity folded into Wl ----
__global__ void prep_B_kernel(const float* __restrict__ W,
                              const float* __restrict__ Wl, int nl) {
    int idx = blockIdx.x * blockDim.x + threadIdx.x;
    int total = nl * 256 * 512;
    if (idx >= total) return;
    int k = idx & 511;
    int nn = (idx >> 9) & 255;
    int l = idx >> 17;
    float w;
    if (k < 256) {
        w = W[((size_t)l * D + k) * D + nn];
    } else {
        w = Wl[((size_t)l * D + (k - 256)) * D + nn];
        if ((k - 256) == nn) w += 1.0f;   // residual h folded in
    }
    __nv_bfloat16 hi = __float2bfloat16(w);
    __nv_bfloat16 lo = __float2bfloat16(w - __bfloat162float(hi));
    g_Bimg_hi[idx] = hi;
    g_Bimg_lo[idx] = lo;
}

__global__ void zero_stats_kernel() {
    if (threadIdx.x < D) {
        g_sum[threadIdx.x] = 0.0f;
        g_sq[threadIdx.x] = 0.0f;
    }
}

// ---- gather aggregate: agg[v] = inv_in[v] * sum_{u in N_in(v)} h[u]*inv_out[u] ----
// one warp per node; gridDim.y selects the 128-feature chunk
__global__ void __launch_bounds__(256)
gather_kernel(const float* __restrict__ h, int n) {
    int node = (blockIdx.x * blockDim.x + threadIdx.x) >> 5;
    if (node >= n) return;
    int lane = threadIdx.x & 31;
    int dimoff = blockIdx.y * 128;
    int e0 = __ldg(&g_rowp[node]);
    int e1 = __ldg(&g_rowp[node + 1]);
    float ax = 0.f, ay = 0.f, az = 0.f, aw = 0.f;
    int ed = e0;
    for (; ed + 2 <= e1; ed += 2) {
        int s0 = __ldg(&g_esrc[ed]);
        int s1 = __ldg(&g_esrc[ed + 1]);
        float c0 = __ldg(&g_inv_out[s0]);
        float c1 = __ldg(&g_inv_out[s1]);
        float4 v0 = __ldg(reinterpret_cast<const float4*>(
            &h[(long)s0 * D + dimoff + lane * 4]));
        float4 v1 = __ldg(reinterpret_cast<const float4*>(
            &h[(long)s1 * D + dimoff + lane * 4]));
        ax += v0.x * c0 + v1.x * c1;
        ay += v0.y * c0 + v1.y * c1;
        az += v0.z * c0 + v1.z * c1;
        aw += v0.w * c0 + v1.w * c1;
    }
    if (ed < e1) {
        int s0 = __ldg(&g_esrc[ed]);
        float c0 = __ldg(&g_inv_out[s0]);
        float4 v0 = __ldg(reinterpret_cast<const float4*>(
            &h[(long)s0 * D + dimoff + lane * 4]));
        ax += v0.x * c0; ay += v0.y * c0; az += v0.z * c0; aw += v0.w * c0;
    }
    float si = g_inv_in[node];
    float4 o = make_float4(ax * si, ay * si, az * si, aw * si);
    *reinterpret_cast<float4*>(&g_agg[(long)node * D + dimoff + lane * 4]) = o;
}

// ---- split-bf16 HMMA GEMM with fused BN column stats ----
// out[128 x 128 tile] = [agg | h] (K=512) @ Bimg^T + b + bl (residual folded).
#define ASTRIDE 40
__global__ void __launch_bounds__(256)
gemm_mma_kernel(const float* __restrict__ h, int layer,
                const float* __restrict__ bvec, const float* __restrict__ blvec,
                int n) {
    __shared__ __nv_bfloat16 sAhi[128 * ASTRIDE];
    __shared__ __nv_bfloat16 sAlo[128 * ASTRIDE];
    __shared__ __nv_bfloat16 sBhi[128 * ASTRIDE];
    __shared__ __nv_bfloat16 sBlo[128 * ASTRIDE];
    __shared__ float s_sum[128];
    __shared__ float s_sq[128];

    int tid = threadIdx.x;
    int wid = tid >> 5, lane = tid & 31;
    int warp_m = wid >> 2;
    int warp_n = wid & 3;
    int rowBase = blockIdx.x * 128;
    int colBase = blockIdx.y * 128;

    if (tid < 128) { s_sum[tid] = 0.0f; s_sq[tid] = 0.0f; }

    uint32_t baseAhi = cvta_s(sAhi), baseAlo = cvta_s(sAlo);
    uint32_t baseBhi = cvta_s(sBhi), baseBlo = cvta_s(sBlo);

    const __nv_bfloat16* imgHi = g_Bimg_hi + (size_t)layer * 256 * 512;
    const __nv_bfloat16* imgLo = g_Bimg_lo + (size_t)layer * 256 * 512;

    float c[4][4][4];
#pragma unroll
    for (int i = 0; i < 4; i++)
#pragma unroll
        for (int j = 0; j < 4; j++)
#pragma unroll
            for (int q = 0; q < 4; q++) c[i][j][q] = 0.0f;

    int lrow = lane & 15;
    int lhalf = lane >> 4;

    for (int kt = 0; kt < 16; kt++) {
#pragma unroll
        for (int i = 0; i < 4; i++) {
            int idx = tid + i * 256;
            int row = idx >> 3, q = idx & 7;
            int grow = rowBase + row;
            float4 v = make_float4(0.f, 0.f, 0.f, 0.f);
            if (grow < n) {
                if (kt < 8) {
                    v = *reinterpret_cast<const float4*>(
                        &g_agg[(long)grow * D + kt * 32 + q * 4]);
                } else {
                    v = *reinterpret_cast<const float4*>(
                        &h[(long)grow * D + (kt - 8) * 32 + q * 4]);
                }
            }
            uint32_t h0, l0, h1, l1;
            split_pair(v.x, v.y, h0, l0);
            split_pair(v.z, v.w, h1, l1);
            *reinterpret_cast<uint2*>(&sAhi[row * ASTRIDE + q * 4]) = make_uint2(h0, h1);
            *reinterpret_cast<uint2*>(&sAlo[row * ASTRIDE + q * 4]) = make_uint2(l0, l1);
        }
#pragma unroll
        for (int i = 0; i < 4; i++) {
            int idx = tid + i * 256;
            int half = idx >> 9;
            int j = idx & 511;
            int nrow = j >> 2, q = j & 3;
            const __nv_bfloat16* srcp = (half ? imgLo : imgHi)
                + ((size_t)(colBase + nrow) * 512 + kt * 32 + q * 8);
            uint4 val = *reinterpret_cast<const uint4*>(srcp);
            __nv_bfloat16* dstp = (half ? sBlo : sBhi) + nrow * ASTRIDE + q * 8;
            *reinterpret_cast<uint2*>(dstp) = make_uint2(val.x, val.y);
            *reinterpret_cast<uint2*>(dstp + 4) = make_uint2(val.z, val.w);
        }
        __syncthreads();

#pragma unroll
        for (int ks = 0; ks < 2; ks++) {
            uint32_t ahi[4][4], alo[4][4];
#pragma unroll
            for (int mt = 0; mt < 4; mt++) {
                uint32_t off = (uint32_t)((warp_m * 64 + mt * 16 + lrow) * 80
                                          + ks * 32 + lhalf * 16);
                ldm_x4(ahi[mt][0], ahi[mt][1], ahi[mt][2], ahi[mt][3], baseAhi + off);
                ldm_x4(alo[mt][0], alo[mt][1], alo[mt][2], alo[mt][3], baseAlo + off);
            }
            uint32_t bhi[4][2], blo[4][2];
#pragma unroll
            for (int np = 0; np < 2; np++) {
                uint32_t off = (uint32_t)((warp_n * 32 + np * 16 + lrow) * 80
                                          + ks * 32 + lhalf * 16);
                uint32_t q0, q1, q2, q3;
                ldm_x4(q0, q1, q2, q3, baseBhi + off);
                bhi[np * 2 + 0][0] = q0; bhi[np * 2 + 0][1] = q2;
                bhi[np * 2 + 1][0] = q1; bhi[np * 2 + 1][1] = q3;
                ldm_x4(q0, q1, q2, q3, baseBlo + off);
                blo[np * 2 + 0][0] = q0; blo[np * 2 + 0][1] = q2;
                blo[np * 2 + 1][0] = q1; blo[np * 2 + 1][1] = q3;
            }
#pragma unroll
            for (int mt = 0; mt < 4; mt++)
#pragma unroll
                for (int nt = 0; nt < 4; nt++) {
                    mma_bf16(c[mt][nt], ahi[mt], bhi[nt][0], bhi[nt][1]);
                    mma_bf16(c[mt][nt], ahi[mt], blo[nt][0], blo[nt][1]);
                    mma_bf16(c[mt][nt], alo[mt], bhi[nt][0], bhi[nt][1]);
                }
        }
        __syncthreads();
    }

    // ---- epilogue: + (b + bl), write g_outb, fused BN column stats ----
#pragma unroll
    for (int nt = 0; nt < 4; nt++) {
        int lc = warp_n * 32 + nt * 8 + (lane & 3) * 2;
        int col = colBase + lc;
        float bx = bvec[col] + blvec[col];
        float by = bvec[col + 1] + blvec[col + 1];
        float csx = 0.f, csy = 0.f, cqx = 0.f, cqy = 0.f;
#pragma unroll
        for (int mt = 0; mt < 4; mt++) {
            int r0 = rowBase + warp_m * 64 + mt * 16 + (lane >> 2);
            if (r0 < n) {
                float vx = c[mt][nt][0] + bx, vy = c[mt][nt][1] + by;
                *reinterpret_cast<float2*>(&g_outb[(long)r0 * D + col]) =
                    make_float2(vx, vy);
                csx += vx; csy += vy; cqx += vx * vx; cqy += vy * vy;
            }
            int r1 = r0 + 8;
            if (r1 < n) {
                float vx = c[mt][nt][2] + bx, vy = c[mt][nt][3] + by;
                *reinterpret_cast<float2*>(&g_outb[(long)r1 * D + col]) =
                    make_float2(vx, vy);
                csx += vx; csy += vy; cqx += vx * vx; cqy += vy * vy;
            }
        }
        atomicAdd(&s_sum[lc], csx);
        atomicAdd(&s_sum[lc + 1], csy);
        atomicAdd(&s_sq[lc], cqx);
        atomicAdd(&s_sq[lc + 1], cqy);
    }
    __syncthreads();
    if (tid < 128) {
        atomicAdd(&g_sum[colBase + tid], s_sum[tid]);
        atomicAdd(&g_sq[colBase + tid], s_sq[tid]);
    }
}

// ---- BN finalize ----
__global__ void bn_fin_kernel(int n) {
    int c = threadIdx.x;
    if (c < D) {
        float inv_n = 1.0f / (float)n;
        float mean = g_sum[c] * inv_n;
        float var = g_sq[c] * inv_n - mean * mean;
        g_mean[c] = mean;
        g_istd[c] = rsqrtf(var + BN_EPS);
    }
}

// ---- normalize + ReLU ----
__global__ void norm_relu_kernel(const float* __restrict__ gamma,
                                 const float* __restrict__ beta,
                                 float* __restrict__ dstp, int n) {
    int total4 = n * (D / 4);
    const float4* o4 = reinterpret_cast<const float4*>(g_outb);
    float4* d4 = reinterpret_cast<float4*>(dstp);
    for (int i = blockIdx.x * blockDim.x + threadIdx.x; i < total4;
         i += gridDim.x * blockDim.x) {
        int c = (i * 4) & (D - 1);
        float4 o = o4[i];
        float4 g = *reinterpret_cast<const float4*>(&gamma[c]);
        float4 be = *reinterpret_cast<const float4*>(&beta[c]);
        float4 m = *reinterpret_cast<const float4*>(&g_mean[c]);
        float4 s = *reinterpret_cast<const float4*>(&g_istd[c]);
        float4 r;
        r.x = fmaxf(g.x * (o.x - m.x) * s.x + be.x, 0.0f);
        r.y = fmaxf(g.y * (o.y - m.y) * s.y + be.y, 0.0f);
        r.z = fmaxf(g.z * (o.z - m.z) * s.z + be.z, 0.0f);
        r.w = fmaxf(g.w * (o.w - m.w) * s.w + be.w, 0.0f);
        d4[i] = r;
    }
}

// ---- host launcher ----
extern "C" void kernel_launch(void* const* d_in, const int* in_sizes, int n_in,
                              void* d_out, int out_size) {
    const float* x     = (const float*)d_in[0];
    const float* W     = (const float*)d_in[1];
    const float* b     = (const float*)d_in[2];
    const float* Wl    = (const float*)d_in[3];
    const float* bl    = (const float*)d_in[4];
    const float* gamma = (const float*)d_in[5];
    const float* beta  = (const float*)d_in[6];
    const int*   src   = (const int*)d_in[7];
    const int*   dst   = (const int*)d_in[8];

    int n = in_sizes[0] / D;
    int e = in_sizes[7];
    int nl = in_sizes[1] / (D * D);

    float* g_h_p = nullptr;
    cudaGetSymbolAddress((void**)&g_h_p, g_h);

    const int T = 256;
    int nblk = (n + T - 1) / T;
    int sblk = (n + SCAN_CHUNK - 1) / SCAN_CHUNK;

    // degrees + CSR (once; graph static across layers)
    zero_deg_kernel<<<nblk, T>>>(n);
    deg_accum_kernel<<<1184, T>>>(src, dst, e);
    deg_fin_kernel<<<nblk, T>>>(n);
    scan1_kernel<<<sblk, 1024>>>(n);
    scan2_kernel<<<1, 32>>>(sblk, n);
    scan3_kernel<<<nblk, T>>>(n);
    bucket_kernel<<<1184, T>>>(src, dst, e);

    // weight prep (all layers)
    int preptasks = nl * 256 * 512;
    prep_B_kernel<<<(preptasks + T - 1) / T, T>>>(W, Wl, nl);

    dim3 gatherg((n * 32 + T - 1) / T, 2);
    const float* hcur = x;
    for (int l = 0; l < nl; l++) {
        zero_stats_kernel<<<1, T>>>();
        gather_kernel<<<gatherg, T>>>(hcur, n);
        dim3 gg((n + 127) / 128, 2);
        gemm_mma_kernel<<<gg, T>>>(hcur, l, b + l * D, bl + l * D, n);
        bn_fin_kernel<<<1, T>>>(n);
        float* dsth = (l == nl - 1) ? (float*)d_out : g_h_p;
        norm_relu_kernel<<<1184, T>>>(gamma + l * D, beta + l * D, dsth, n);
        hcur = g_h_p;
    }
}

// round 9
// speedup vs baseline: 2.4210x; 1.0944x over previous
#include <cuda_runtime.h>
#include <cuda_bf16.h>
#include <cuda_fp16.h>
#include <cstdint>

#define D 256
#define MAXN 100000
#define MAXE 3200000
#define BN_EPS 1e-5f
#define LMAX 3
#define SCAN_CHUNK 4096

// ---- scratch (static device globals; no allocation allowed) ----
__device__ __align__(128) float g_h[MAXN * D];
__device__ __align__(128) __half g_h16[MAXN * D];   // fp16 image for gather
__device__ __align__(128) float g_agg[MAXN * D];
__device__ __align__(128) float g_outb[MAXN * D];
__device__ float g_inv_out[MAXN];
__device__ float g_inv_in[MAXN];
__device__ int   g_degi_out[MAXN];
__device__ int   g_degi_in[MAXN];
__device__ int   g_rowp[MAXN + 1];
__device__ int   g_cursor[MAXN];
__device__ int   g_esrc[MAXE];
__device__ int   g_bsum[128];
__device__ int   g_boff[128];
__device__ float g_sum[D];
__device__ float g_sq[D];
__device__ float g_mean[D];
__device__ float g_istd[D];
// Weight images: B^T layout [L][n=256][k=512] bf16, hi and lo halves.
__device__ __align__(128) __nv_bfloat16 g_Bimg_hi[LMAX * 256 * 512];
__device__ __align__(128) __nv_bfloat16 g_Bimg_lo[LMAX * 256 * 512];

// ---- helpers ----
__device__ __forceinline__ uint32_t cvta_s(const void* p) {
    uint32_t a;
    asm("{ .reg .u64 t; cvta.to.shared.u64 t, %1; cvt.u32.u64 %0, t; }"
        : "=r"(a) : "l"(p));
    return a;
}
__device__ __forceinline__ void ldm_x4(uint32_t& r0, uint32_t& r1,
                                       uint32_t& r2, uint32_t& r3, uint32_t a) {
    asm volatile("ldmatrix.sync.aligned.m8n8.x4.shared.b16 {%0,%1,%2,%3}, [%4];"
                 : "=r"(r0), "=r"(r1), "=r"(r2), "=r"(r3) : "r"(a));
}
__device__ __forceinline__ void mma_bf16(float* c, const uint32_t* a,
                                         uint32_t b0, uint32_t b1) {
    asm volatile(
        "mma.sync.aligned.m16n8k16.row.col.f32.bf16.bf16.f32 "
        "{%0,%1,%2,%3}, {%4,%5,%6,%7}, {%8,%9}, {%0,%1,%2,%3};"
        : "+f"(c[0]), "+f"(c[1]), "+f"(c[2]), "+f"(c[3])
        : "r"(a[0]), "r"(a[1]), "r"(a[2]), "r"(a[3]), "r"(b0), "r"(b1));
}
__device__ __forceinline__ uint32_t pack_bf2(__nv_bfloat16 a, __nv_bfloat16 b) {
    return (uint32_t)__bfloat16_as_ushort(a) | ((uint32_t)__bfloat16_as_ushort(b) << 16);
}
__device__ __forceinline__ void split_pair(float x, float y, uint32_t& hi, uint32_t& lo) {
    __nv_bfloat16 hx = __float2bfloat16(x);
    __nv_bfloat16 hy = __float2bfloat16(y);
    float rx = x - __bfloat162float(hx);
    float ry = y - __bfloat162float(hy);
    hi = pack_bf2(hx, hy);
    lo = pack_bf2(__float2bfloat16(rx), __float2bfloat16(ry));
}

// ---- degree / CSR build ----
__global__ void zero_deg_kernel(int n) {
    for (int i = blockIdx.x * blockDim.x + threadIdx.x; i < n;
         i += gridDim.x * blockDim.x) {
        g_degi_out[i] = 0;
        g_degi_in[i] = 0;
    }
}
__global__ void deg_accum_kernel(const int* __restrict__ src,
                                 const int* __restrict__ dst, int e) {
    for (int i = blockIdx.x * blockDim.x + threadIdx.x; i < e;
         i += gridDim.x * blockDim.x) {
        atomicAdd(&g_degi_out[src[i]], 1);
        atomicAdd(&g_degi_in[dst[i]], 1);
    }
}
__global__ void deg_fin_kernel(int n) {
    for (int i = blockIdx.x * blockDim.x + threadIdx.x; i < n;
         i += gridDim.x * blockDim.x) {
        g_inv_out[i] = rsqrtf(fmaxf((float)g_degi_out[i], 1.0f));
        g_inv_in[i]  = rsqrtf(fmaxf((float)g_degi_in[i], 1.0f));
    }
}
__global__ void __launch_bounds__(1024)
scan1_kernel(int n) {
    __shared__ int wsum[32];
    int t = threadIdx.x;
    int lane = t & 31, w = t >> 5;
    int base = blockIdx.x * SCAN_CHUNK + t * 4;
    int v0 = (base + 0 < n) ? g_degi_in[base + 0] : 0;
    int v1 = (base + 1 < n) ? g_degi_in[base + 1] : 0;
    int v2 = (base + 2 < n) ? g_degi_in[base + 2] : 0;
    int v3 = (base + 3 < n) ? g_degi_in[base + 3] : 0;
    int s = v0 + v1 + v2 + v3;
    int inc = s;
#pragma unroll
    for (int o = 1; o < 32; o <<= 1) {
        int u = __shfl_up_sync(0xFFFFFFFFu, inc, o);
        if (lane >= o) inc += u;
    }
    if (lane == 31) wsum[w] = inc;
    __syncthreads();
    if (w == 0) {
        int ws = wsum[lane];
#pragma unroll
        for (int o = 1; o < 32; o <<= 1) {
            int u = __shfl_up_sync(0xFFFFFFFFu, ws, o);
            if (lane >= o) ws += u;
        }
        wsum[lane] = ws;
    }
    __syncthreads();
    int excl = inc - s + (w > 0 ? wsum[w - 1] : 0);
    if (base + 0 < n) g_rowp[base + 0] = excl;
    if (base + 1 < n) g_rowp[base + 1] = excl + v0;
    if (base + 2 < n) g_rowp[base + 2] = excl + v0 + v1;
    if (base + 3 < n) g_rowp[base + 3] = excl + v0 + v1 + v2;
    if (t == 1023) g_bsum[blockIdx.x] = wsum[31];
}
__global__ void scan2_kernel(int nblk, int n) {
    if (threadIdx.x == 0) {
        int run = 0;
        for (int b = 0; b < nblk; b++) {
            g_boff[b] = run;
            run += g_bsum[b];
        }
        g_rowp[n] = run;
    }
}
__global__ void scan3_kernel(int n) {
    for (int i = blockIdx.x * blockDim.x + threadIdx.x; i < n;
         i += gridDim.x * blockDim.x) {
        int v = g_rowp[i] + g_boff[i / SCAN_CHUNK];
        g_rowp[i] = v;
        g_cursor[i] = v;
    }
}
__global__ void bucket_kernel(const int* __restrict__ src,
                              const int* __restrict__ dst, int e) {
    for (int i = blockIdx.x * blockDim.x + threadIdx.x; i < e;
         i += gridDim.x * blockDim.x) {
        int pos = atomicAdd(&g_cursor[dst[i]], 1);
        g_esrc[pos] = src[i];
    }
}

// ---- weight prep ----
__global__ void prep_B_kernel(const float* __restrict__ W,
                              const float* __restrict__ Wl, int nl) {
    int idx = blockIdx.x * blockDim.x + threadIdx.x;
    int total = nl * 256 * 512;
    if (idx >= total) return;
    int k = idx & 511;
    int nn = (idx >> 9) & 255;
    int l = idx >> 17;
    float w;
    if (k < 256) {
        w = W[((size_t)l * D + k) * D + nn];
    } else {
        w = Wl[((size_t)l * D + (k - 256)) * D + nn];
        if ((k - 256) == nn) w += 1.0f;
    }
    __nv_bfloat16 hi = __float2bfloat16(w);
    __nv_bfloat16 lo = __float2bfloat16(w - __bfloat162float(hi));
    g_Bimg_hi[idx] = hi;
    g_Bimg_lo[idx] = lo;
}

__global__ void zero_stats_kernel() {
    if (threadIdx.x < D) {
        g_sum[threadIdx.x] = 0.0f;
        g_sq[threadIdx.x] = 0.0f;
    }
}

// ---- x -> fp16 image (once) ----
__global__ void x16_kernel(const float* __restrict__ x, int n) {
    int total4 = n * (D / 4);
    const float4* x4 = reinterpret_cast<const float4*>(x);
    __half2* o2 = reinterpret_cast<__half2*>(g_h16);
    for (int i = blockIdx.x * blockDim.x + threadIdx.x; i < total4;
         i += gridDim.x * blockDim.x) {
        float4 v = x4[i];
        o2[i * 2 + 0] = __floats2half2_rn(v.x, v.y);
        o2[i * 2 + 1] = __floats2half2_rn(v.z, v.w);
    }
}

// ---- gather aggregate (fp16 source, fp32 accum), full 256-feature row ----
// one warp per node; lane handles 8 contiguous features (16B fp16)
__global__ void __launch_bounds__(256)
gather_kernel(int n) {
    int node = (blockIdx.x * blockDim.x + threadIdx.x) >> 5;
    if (node >= n) return;
    int lane = threadIdx.x & 31;
    int e0 = __ldg(&g_rowp[node]);
    int e1 = __ldg(&g_rowp[node + 1]);
    float a0 = 0.f, a1 = 0.f, a2 = 0.f, a3 = 0.f;
    float a4 = 0.f, a5 = 0.f, a6 = 0.f, a7 = 0.f;
    int ed = e0;
    for (; ed + 2 <= e1; ed += 2) {
        int s0 = __ldg(&g_esrc[ed]);
        int s1 = __ldg(&g_esrc[ed + 1]);
        float c0 = __ldg(&g_inv_out[s0]);
        float c1 = __ldg(&g_inv_out[s1]);
        uint4 u0 = __ldg(reinterpret_cast<const uint4*>(
            &g_h16[(long)s0 * D + lane * 8]));
        uint4 u1 = __ldg(reinterpret_cast<const uint4*>(
            &g_h16[(long)s1 * D + lane * 8]));
        float2 f;
        f = __half22float2(*reinterpret_cast<__half2*>(&u0.x)); a0 += f.x * c0; a1 += f.y * c0;
        f = __half22float2(*reinterpret_cast<__half2*>(&u0.y)); a2 += f.x * c0; a3 += f.y * c0;
        f = __half22float2(*reinterpret_cast<__half2*>(&u0.z)); a4 += f.x * c0; a5 += f.y * c0;
        f = __half22float2(*reinterpret_cast<__half2*>(&u0.w)); a6 += f.x * c0; a7 += f.y * c0;
        f = __half22float2(*reinterpret_cast<__half2*>(&u1.x)); a0 += f.x * c1; a1 += f.y * c1;
        f = __half22float2(*reinterpret_cast<__half2*>(&u1.y)); a2 += f.x * c1; a3 += f.y * c1;
        f = __half22float2(*reinterpret_cast<__half2*>(&u1.z)); a4 += f.x * c1; a5 += f.y * c1;
        f = __half22float2(*reinterpret_cast<__half2*>(&u1.w)); a6 += f.x * c1; a7 += f.y * c1;
    }
    if (ed < e1) {
        int s0 = __ldg(&g_esrc[ed]);
        float c0 = __ldg(&g_inv_out[s0]);
        uint4 u0 = __ldg(reinterpret_cast<const uint4*>(
            &g_h16[(long)s0 * D + lane * 8]));
        float2 f;
        f = __half22float2(*reinterpret_cast<__half2*>(&u0.x)); a0 += f.x * c0; a1 += f.y * c0;
        f = __half22float2(*reinterpret_cast<__half2*>(&u0.y)); a2 += f.x * c0; a3 += f.y * c0;
        f = __half22float2(*reinterpret_cast<__half2*>(&u0.z)); a4 += f.x * c0; a5 += f.y * c0;
        f = __half22float2(*reinterpret_cast<__half2*>(&u0.w)); a6 += f.x * c0; a7 += f.y * c0;
    }
    float si = g_inv_in[node];
    float* op = &g_agg[(long)node * D + lane * 8];
    *reinterpret_cast<float4*>(op) =
        make_float4(a0 * si, a1 * si, a2 * si, a3 * si);
    *reinterpret_cast<float4*>(op + 4) =
        make_float4(a4 * si, a5 * si, a6 * si, a7 * si);
}

// ---- split-bf16 HMMA GEMM with fused BN column stats ----
#define ASTRIDE 40
__global__ void __launch_bounds__(256)
gemm_mma_kernel(const float* __restrict__ h, int layer,
                const float* __restrict__ bvec, const float* __restrict__ blvec,
                int n) {
    __shared__ __nv_bfloat16 sAhi[128 * ASTRIDE];
    __shared__ __nv_bfloat16 sAlo[128 * ASTRIDE];
    __shared__ __nv_bfloat16 sBhi[128 * ASTRIDE];
    __shared__ __nv_bfloat16 sBlo[128 * ASTRIDE];
    __shared__ float s_sum[128];
    __shared__ float s_sq[128];

    int tid = threadIdx.x;
    int wid = tid >> 5, lane = tid & 31;
    int warp_m = wid >> 2;
    int warp_n = wid & 3;
    int rowBase = blockIdx.x * 128;
    int colBase = blockIdx.y * 128;

    if (tid < 128) { s_sum[tid] = 0.0f; s_sq[tid] = 0.0f; }

    uint32_t baseAhi = cvta_s(sAhi), baseAlo = cvta_s(sAlo);
    uint32_t baseBhi = cvta_s(sBhi), baseBlo = cvta_s(sBlo);

    const __nv_bfloat16* imgHi = g_Bimg_hi + (size_t)layer * 256 * 512;
    const __nv_bfloat16* imgLo = g_Bimg_lo + (size_t)layer * 256 * 512;

    float c[4][4][4];
#pragma unroll
    for (int i = 0; i < 4; i++)
#pragma unroll
        for (int j = 0; j < 4; j++)
#pragma unroll
            for (int q = 0; q < 4; q++) c[i][j][q] = 0.0f;

    int lrow = lane & 15;
    int lhalf = lane >> 4;

    for (int kt = 0; kt < 16; kt++) {
#pragma unroll
        for (int i = 0; i < 4; i++) {
            int idx = tid + i * 256;
            int row = idx >> 3, q = idx & 7;
            int grow = rowBase + row;
            float4 v = make_float4(0.f, 0.f, 0.f, 0.f);
            if (grow < n) {
                if (kt < 8) {
                    v = *reinterpret_cast<const float4*>(
                        &g_agg[(long)grow * D + kt * 32 + q * 4]);
                } else {
                    v = *reinterpret_cast<const float4*>(
                        &h[(long)grow * D + (kt - 8) * 32 + q * 4]);
                }
            }
            uint32_t h0, l0, h1, l1;
            split_pair(v.x, v.y, h0, l0);
            split_pair(v.z, v.w, h1, l1);
            *reinterpret_cast<uint2*>(&sAhi[row * ASTRIDE + q * 4]) = make_uint2(h0, h1);
            *reinterpret_cast<uint2*>(&sAlo[row * ASTRIDE + q * 4]) = make_uint2(l0, l1);
        }
#pragma unroll
        for (int i = 0; i < 4; i++) {
            int idx = tid + i * 256;
            int half = idx >> 9;
            int j = idx & 511;
            int nrow = j >> 2, q = j & 3;
            const __nv_bfloat16* srcp = (half ? imgLo : imgHi)
                + ((size_t)(colBase + nrow) * 512 + kt * 32 + q * 8);
            uint4 val = *reinterpret_cast<const uint4*>(srcp);
            __nv_bfloat16* dstp = (half ? sBlo : sBhi) + nrow * ASTRIDE + q * 8;
            *reinterpret_cast<uint2*>(dstp) = make_uint2(val.x, val.y);
            *reinterpret_cast<uint2*>(dstp + 4) = make_uint2(val.z, val.w);
        }
        __syncthreads();

#pragma unroll
        for (int ks = 0; ks < 2; ks++) {
            uint32_t ahi[4][4], alo[4][4];
#pragma unroll
            for (int mt = 0; mt < 4; mt++) {
                uint32_t off = (uint32_t)((warp_m * 64 + mt * 16 + lrow) * 80
                                          + ks * 32 + lhalf * 16);
                ldm_x4(ahi[mt][0], ahi[mt][1], ahi[mt][2], ahi[mt][3], baseAhi + off);
                ldm_x4(alo[mt][0], alo[mt][1], alo[mt][2], alo[mt][3], baseAlo + off);
            }
            uint32_t bhi[4][2], blo[4][2];
#pragma unroll
            for (int np = 0; np < 2; np++) {
                uint32_t off = (uint32_t)((warp_n * 32 + np * 16 + lrow) * 80
                                          + ks * 32 + lhalf * 16);
                uint32_t q0, q1, q2, q3;
                ldm_x4(q0, q1, q2, q3, baseBhi + off);
                bhi[np * 2 + 0][0] = q0; bhi[np * 2 + 0][1] = q2;
                bhi[np * 2 + 1][0] = q1; bhi[np * 2 + 1][1] = q3;
                ldm_x4(q0, q1, q2, q3, baseBlo + off);
                blo[np * 2 + 0][0] = q0; blo[np * 2 + 0][1] = q2;
                blo[np * 2 + 1][0] = q1; blo[np * 2 + 1][1] = q3;
            }
#pragma unroll
            for (int mt = 0; mt < 4; mt++)
#pragma unroll
                for (int nt = 0; nt < 4; nt++) {
                    mma_bf16(c[mt][nt], ahi[mt], bhi[nt][0], bhi[nt][1]);
                    mma_bf16(c[mt][nt], ahi[mt], blo[nt][0], blo[nt][1]);
                    mma_bf16(c[mt][nt], alo[mt], bhi[nt][0], bhi[nt][1]);
                }
        }
        __syncthreads();
    }

#pragma unroll
    for (int nt = 0; nt < 4; nt++) {
        int lc = warp_n * 32 + nt * 8 + (lane & 3) * 2;
        int col = colBase + lc;
        float bx = bvec[col] + blvec[col];
        float by = bvec[col + 1] + blvec[col + 1];
        float csx = 0.f, csy = 0.f, cqx = 0.f, cqy = 0.f;
#pragma unroll
        for (int mt = 0; mt < 4; mt++) {
            int r0 = rowBase + warp_m * 64 + mt * 16 + (lane >> 2);
            if (r0 < n) {
                float vx = c[mt][nt][0] + bx, vy = c[mt][nt][1] + by;
                *reinterpret_cast<float2*>(&g_outb[(long)r0 * D + col]) =
                    make_float2(vx, vy);
                csx += vx; csy += vy; cqx += vx * vx; cqy += vy * vy;
            }
            int r1 = r0 + 8;
            if (r1 < n) {
                float vx = c[mt][nt][2] + bx, vy = c[mt][nt][3] + by;
                *reinterpret_cast<float2*>(&g_outb[(long)r1 * D + col]) =
                    make_float2(vx, vy);
                csx += vx; csy += vy; cqx += vx * vx; cqy += vy * vy;
            }
        }
        atomicAdd(&s_sum[lc], csx);
        atomicAdd(&s_sum[lc + 1], csy);
        atomicAdd(&s_sq[lc], cqx);
        atomicAdd(&s_sq[lc + 1], cqy);
    }
    __syncthreads();
    if (tid < 128) {
        atomicAdd(&g_sum[colBase + tid], s_sum[tid]);
        atomicAdd(&g_sq[colBase + tid], s_sq[tid]);
    }
}

// ---- BN finalize ----
__global__ void bn_fin_kernel(int n) {
    int c = threadIdx.x;
    if (c < D) {
        float inv_n = 1.0f / (float)n;
        float mean = g_sum[c] * inv_n;
        float var = g_sq[c] * inv_n - mean * mean;
        g_mean[c] = mean;
        g_istd[c] = rsqrtf(var + BN_EPS);
    }
}

// ---- normalize + ReLU (writes fp32 dst; optional fp16 image for next gather) ----
__global__ void norm_relu_kernel(const float* __restrict__ gamma,
                                 const float* __restrict__ beta,
                                 float* __restrict__ dstp, int n, int write16) {
    int total4 = n * (D / 4);
    const float4* o4 = reinterpret_cast<const float4*>(g_outb);
    float4* d4 = reinterpret_cast<float4*>(dstp);
    __half2* h2 = reinterpret_cast<__half2*>(g_h16);
    for (int i = blockIdx.x * blockDim.x + threadIdx.x; i < total4;
         i += gridDim.x * blockDim.x) {
        int c = (i * 4) & (D - 1);
        float4 o = o4[i];
        float4 g = *reinterpret_cast<const float4*>(&gamma[c]);
        float4 be = *reinterpret_cast<const float4*>(&beta[c]);
        float4 m = *reinterpret_cast<const float4*>(&g_mean[c]);
        float4 s = *reinterpret_cast<const float4*>(&g_istd[c]);
        float4 r;
        r.x = fmaxf(g.x * (o.x - m.x) * s.x + be.x, 0.0f);
        r.y = fmaxf(g.y * (o.y - m.y) * s.y + be.y, 0.0f);
        r.z = fmaxf(g.z * (o.z - m.z) * s.z + be.z, 0.0f);
        r.w = fmaxf(g.w * (o.w - m.w) * s.w + be.w, 0.0f);
        d4[i] = r;
        if (write16) {
            h2[i * 2 + 0] = __floats2half2_rn(r.x, r.y);
            h2[i * 2 + 1] = __floats2half2_rn(r.z, r.w);
        }
    }
}

// ---- host launcher ----
extern "C" void kernel_launch(void* const* d_in, const int* in_sizes, int n_in,
                              void* d_out, int out_size) {
    const float* x     = (const float*)d_in[0];
    const float* W     = (const float*)d_in[1];
    const float* b     = (const float*)d_in[2];
    const float* Wl    = (const float*)d_in[3];
    const float* bl    = (const float*)d_in[4];
    const float* gamma = (const float*)d_in[5];
    const float* beta  = (const float*)d_in[6];
    const int*   src   = (const int*)d_in[7];
    const int*   dst   = (const int*)d_in[8];

    int n = in_sizes[0] / D;
    int e = in_sizes[7];
    int nl = in_sizes[1] / (D * D);

    float* g_h_p = nullptr;
    cudaGetSymbolAddress((void**)&g_h_p, g_h);

    const int T = 256;
    int nblk = (n + T - 1) / T;
    int sblk = (n + SCAN_CHUNK - 1) / SCAN_CHUNK;

    // degrees + CSR (once; graph static across layers)
    zero_deg_kernel<<<nblk, T>>>(n);
    deg_accum_kernel<<<1184, T>>>(src, dst, e);
    deg_fin_kernel<<<nblk, T>>>(n);
    scan1_kernel<<<sblk, 1024>>>(n);
    scan2_kernel<<<1, 32>>>(sblk, n);
    scan3_kernel<<<nblk, T>>>(n);
    bucket_kernel<<<1184, T>>>(src, dst, e);

    // weight prep + fp16 image of x
    int preptasks = nl * 256 * 512;
    prep_B_kernel<<<(preptasks + T - 1) / T, T>>>(W, Wl, nl);
    x16_kernel<<<1184, T>>>(x, n);

    int gatherb = (n * 32 + T - 1) / T;
    const float* hcur = x;
    for (int l = 0; l < nl; l++) {
        zero_stats_kernel<<<1, T>>>();
        gather_kernel<<<gatherb, T>>>(n);
        dim3 gg((n + 127) / 128, 2);
        gemm_mma_kernel<<<gg, T>>>(hcur, l, b + l * D, bl + l * D, n);
        bn_fin_kernel<<<1, T>>>(n);
        float* dsth = (l == nl - 1) ? (float*)d_out : g_h_p;
        norm_relu_kernel<<<1184, T>>>(gamma + l * D, beta + l * D, dsth, n,
                                      (l < nl - 1) ? 1 : 0);
        hcur = g_h_p;
    }
}

// round 10
// speedup vs baseline: 2.4557x; 1.0144x over previous
#include <cuda_runtime.h>
#include <cuda_bf16.h>
#include <cuda_fp16.h>
#include <cstdint>

#define D 256
#define MAXN 100000
#define NPAD (MAXN + 128)
#define MAXE 3200000
#define BN_EPS 1e-5f
#define LMAX 3
#define SCAN_CHUNK 4096

// ---- scratch (static device globals; no allocation allowed) ----
__device__ __align__(128) __half g_h16[MAXN * D];          // fp16 image for gather
__device__ __align__(128) float g_outb[MAXN * D];          // pre-BN output
// A operand split-bf16 images: [node][k=0..511] (k<256: agg, k>=256: h)
__device__ __align__(128) __nv_bfloat16 g_A_hi[NPAD * 512];
__device__ __align__(128) __nv_bfloat16 g_A_lo[NPAD * 512];
__device__ float g_inv_out[MAXN];
__device__ float g_inv_in[MAXN];
__device__ int   g_degi_out[MAXN];
__device__ int   g_degi_in[MAXN];
__device__ int   g_rowp[MAXN + 1];
__device__ int   g_cursor[MAXN];
__device__ int   g_esrc[MAXE];
__device__ int   g_bsum[128];
__device__ int   g_boff[128];
__device__ float g_sum[D];
__device__ float g_sq[D];
__device__ float g_mean[D];
__device__ float g_istd[D];
// Weight images: B^T layout [L][n=256][k=512] bf16, hi and lo halves.
__device__ __align__(128) __nv_bfloat16 g_Bimg_hi[LMAX * 256 * 512];
__device__ __align__(128) __nv_bfloat16 g_Bimg_lo[LMAX * 256 * 512];

// ---- helpers ----
__device__ __forceinline__ uint32_t cvta_s(const void* p) {
    uint32_t a;
    asm("{ .reg .u64 t; cvta.to.shared.u64 t, %1; cvt.u32.u64 %0, t; }"
        : "=r"(a) : "l"(p));
    return a;
}
__device__ __forceinline__ void ldm_x4(uint32_t& r0, uint32_t& r1,
                                       uint32_t& r2, uint32_t& r3, uint32_t a) {
    asm volatile("ldmatrix.sync.aligned.m8n8.x4.shared.b16 {%0,%1,%2,%3}, [%4];"
                 : "=r"(r0), "=r"(r1), "=r"(r2), "=r"(r3) : "r"(a));
}
__device__ __forceinline__ void mma_bf16(float* c, const uint32_t* a,
                                         uint32_t b0, uint32_t b1) {
    asm volatile(
        "mma.sync.aligned.m16n8k16.row.col.f32.bf16.bf16.f32 "
        "{%0,%1,%2,%3}, {%4,%5,%6,%7}, {%8,%9}, {%0,%1,%2,%3};"
        : "+f"(c[0]), "+f"(c[1]), "+f"(c[2]), "+f"(c[3])
        : "r"(a[0]), "r"(a[1]), "r"(a[2]), "r"(a[3]), "r"(b0), "r"(b1));
}
__device__ __forceinline__ uint32_t pack_bf2(__nv_bfloat16 a, __nv_bfloat16 b) {
    return (uint32_t)__bfloat16_as_ushort(a) | ((uint32_t)__bfloat16_as_ushort(b) << 16);
}
__device__ __forceinline__ void split_pair(float x, float y, uint32_t& hi, uint32_t& lo) {
    __nv_bfloat16 hx = __float2bfloat16(x);
    __nv_bfloat16 hy = __float2bfloat16(y);
    float rx = x - __bfloat162float(hx);
    float ry = y - __bfloat162float(hy);
    hi = pack_bf2(hx, hy);
    lo = pack_bf2(__float2bfloat16(rx), __float2bfloat16(ry));
}

// ---- degree / CSR build ----
__global__ void zero_deg_kernel(int n) {
    for (int i = blockIdx.x * blockDim.x + threadIdx.x; i < n;
         i += gridDim.x * blockDim.x) {
        g_degi_out[i] = 0;
        g_degi_in[i] = 0;
    }
}
__global__ void deg_accum_kernel(const int* __restrict__ src,
                                 const int* __restrict__ dst, int e) {
    for (int i = blockIdx.x * blockDim.x + threadIdx.x; i < e;
         i += gridDim.x * blockDim.x) {
        atomicAdd(&g_degi_out[src[i]], 1);
        atomicAdd(&g_degi_in[dst[i]], 1);
    }
}
__global__ void deg_fin_kernel(int n) {
    for (int i = blockIdx.x * blockDim.x + threadIdx.x; i < n;
         i += gridDim.x * blockDim.x) {
        g_inv_out[i] = rsqrtf(fmaxf((float)g_degi_out[i], 1.0f));
        g_inv_in[i]  = rsqrtf(fmaxf((float)g_degi_in[i], 1.0f));
    }
}
__global__ void __launch_bounds__(1024)
scan1_kernel(int n) {
    __shared__ int wsum[32];
    int t = threadIdx.x;
    int lane = t & 31, w = t >> 5;
    int base = blockIdx.x * SCAN_CHUNK + t * 4;
    int v0 = (base + 0 < n) ? g_degi_in[base + 0] : 0;
    int v1 = (base + 1 < n) ? g_degi_in[base + 1] : 0;
    int v2 = (base + 2 < n) ? g_degi_in[base + 2] : 0;
    int v3 = (base + 3 < n) ? g_degi_in[base + 3] : 0;
    int s = v0 + v1 + v2 + v3;
    int inc = s;
#pragma unroll
    for (int o = 1; o < 32; o <<= 1) {
        int u = __shfl_up_sync(0xFFFFFFFFu, inc, o);
        if (lane >= o) inc += u;
    }
    if (lane == 31) wsum[w] = inc;
    __syncthreads();
    if (w == 0) {
        int ws = wsum[lane];
#pragma unroll
        for (int o = 1; o < 32; o <<= 1) {
            int u = __shfl_up_sync(0xFFFFFFFFu, ws, o);
            if (lane >= o) ws += u;
        }
        wsum[lane] = ws;
    }
    __syncthreads();
    int excl = inc - s + (w > 0 ? wsum[w - 1] : 0);
    if (base + 0 < n) g_rowp[base + 0] = excl;
    if (base + 1 < n) g_rowp[base + 1] = excl + v0;
    if (base + 2 < n) g_rowp[base + 2] = excl + v0 + v1;
    if (base + 3 < n) g_rowp[base + 3] = excl + v0 + v1 + v2;
    if (t == 1023) g_bsum[blockIdx.x] = wsum[31];
}
__global__ void scan2_kernel(int nblk, int n) {
    if (threadIdx.x == 0) {
        int run = 0;
        for (int b = 0; b < nblk; b++) {
            g_boff[b] = run;
            run += g_bsum[b];
        }
        g_rowp[n] = run;
    }
}
__global__ void scan3_kernel(int n) {
    for (int i = blockIdx.x * blockDim.x + threadIdx.x; i < n;
         i += gridDim.x * blockDim.x) {
        int v = g_rowp[i] + g_boff[i / SCAN_CHUNK];
        g_rowp[i] = v;
        g_cursor[i] = v;
    }
}
__global__ void bucket_kernel(const int* __restrict__ src,
                              const int* __restrict__ dst, int e) {
    for (int i = blockIdx.x * blockDim.x + threadIdx.x; i < e;
         i += gridDim.x * blockDim.x) {
        int pos = atomicAdd(&g_cursor[dst[i]], 1);
        g_esrc[pos] = src[i];
    }
}

// ---- weight prep ----
__global__ void prep_B_kernel(const float* __restrict__ W,
                              const float* __restrict__ Wl, int nl) {
    int idx = blockIdx.x * blockDim.x + threadIdx.x;
    int total = nl * 256 * 512;
    if (idx >= total) return;
    int k = idx & 511;
    int nn = (idx >> 9) & 255;
    int l = idx >> 17;
    float w;
    if (k < 256) {
        w = W[((size_t)l * D + k) * D + nn];
    } else {
        w = Wl[((size_t)l * D + (k - 256)) * D + nn];
        if ((k - 256) == nn) w += 1.0f;
    }
    __nv_bfloat16 hi = __float2bfloat16(w);
    __nv_bfloat16 lo = __float2bfloat16(w - __bfloat162float(hi));
    g_Bimg_hi[idx] = hi;
    g_Bimg_lo[idx] = lo;
}

__global__ void zero_stats_kernel() {
    if (threadIdx.x < D) {
        g_sum[threadIdx.x] = 0.0f;
        g_sq[threadIdx.x] = 0.0f;
    }
}

// ---- x prep (once): fp16 image + h-half of A split images ----
__global__ void xprep_kernel(const float* __restrict__ x, int n) {
    int total4 = n * (D / 4);
    const float4* x4 = reinterpret_cast<const float4*>(x);
    __half2* o2 = reinterpret_cast<__half2*>(g_h16);
    for (int i = blockIdx.x * blockDim.x + threadIdx.x; i < total4;
         i += gridDim.x * blockDim.x) {
        float4 v = x4[i];
        o2[i * 2 + 0] = __floats2half2_rn(v.x, v.y);
        o2[i * 2 + 1] = __floats2half2_rn(v.z, v.w);
        int node = i >> 6;
        int c = (i & 63) * 4;
        uint32_t h0, l0, h1, l1;
        split_pair(v.x, v.y, h0, l0);
        split_pair(v.z, v.w, h1, l1);
        long off = (long)node * 512 + 256 + c;
        *reinterpret_cast<uint2*>(&g_A_hi[off]) = make_uint2(h0, h1);
        *reinterpret_cast<uint2*>(&g_A_lo[off]) = make_uint2(l0, l1);
    }
}

// ---- gather aggregate (fp16 source, fp32 accum) -> split-bf16 agg image ----
// one warp per node; lane handles 8 contiguous features
__global__ void __launch_bounds__(256)
gather_kernel(int n) {
    int node = (blockIdx.x * blockDim.x + threadIdx.x) >> 5;
    if (node >= n) return;
    int lane = threadIdx.x & 31;
    int e0 = __ldg(&g_rowp[node]);
    int e1 = __ldg(&g_rowp[node + 1]);
    float a0 = 0.f, a1 = 0.f, a2 = 0.f, a3 = 0.f;
    float a4 = 0.f, a5 = 0.f, a6 = 0.f, a7 = 0.f;
    int ed = e0;
    for (; ed + 4 <= e1; ed += 4) {
        int s0 = __ldg(&g_esrc[ed]);
        int s1 = __ldg(&g_esrc[ed + 1]);
        int s2 = __ldg(&g_esrc[ed + 2]);
        int s3 = __ldg(&g_esrc[ed + 3]);
        float c0 = __ldg(&g_inv_out[s0]);
        float c1 = __ldg(&g_inv_out[s1]);
        float c2 = __ldg(&g_inv_out[s2]);
        float c3 = __ldg(&g_inv_out[s3]);
        uint4 u0 = __ldg(reinterpret_cast<const uint4*>(&g_h16[(long)s0 * D + lane * 8]));
        uint4 u1 = __ldg(reinterpret_cast<const uint4*>(&g_h16[(long)s1 * D + lane * 8]));
        uint4 u2 = __ldg(reinterpret_cast<const uint4*>(&g_h16[(long)s2 * D + lane * 8]));
        uint4 u3 = __ldg(reinterpret_cast<const uint4*>(&g_h16[(long)s3 * D + lane * 8]));
        float2 f;
        f = __half22float2(*reinterpret_cast<__half2*>(&u0.x)); a0 += f.x * c0; a1 += f.y * c0;
        f = __half22float2(*reinterpret_cast<__half2*>(&u0.y)); a2 += f.x * c0; a3 += f.y * c0;
        f = __half22float2(*reinterpret_cast<__half2*>(&u0.z)); a4 += f.x * c0; a5 += f.y * c0;
        f = __half22float2(*reinterpret_cast<__half2*>(&u0.w)); a6 += f.x * c0; a7 += f.y * c0;
        f = __half22float2(*reinterpret_cast<__half2*>(&u1.x)); a0 += f.x * c1; a1 += f.y * c1;
        f = __half22float2(*reinterpret_cast<__half2*>(&u1.y)); a2 += f.x * c1; a3 += f.y * c1;
        f = __half22float2(*reinterpret_cast<__half2*>(&u1.z)); a4 += f.x * c1; a5 += f.y * c1;
        f = __half22float2(*reinterpret_cast<__half2*>(&u1.w)); a6 += f.x * c1; a7 += f.y * c1;
        f = __half22float2(*reinterpret_cast<__half2*>(&u2.x)); a0 += f.x * c2; a1 += f.y * c2;
        f = __half22float2(*reinterpret_cast<__half2*>(&u2.y)); a2 += f.x * c2; a3 += f.y * c2;
        f = __half22float2(*reinterpret_cast<__half2*>(&u2.z)); a4 += f.x * c2; a5 += f.y * c2;
        f = __half22float2(*reinterpret_cast<__half2*>(&u2.w)); a6 += f.x * c2; a7 += f.y * c2;
        f = __half22float2(*reinterpret_cast<__half2*>(&u3.x)); a0 += f.x * c3; a1 += f.y * c3;
        f = __half22float2(*reinterpret_cast<__half2*>(&u3.y)); a2 += f.x * c3; a3 += f.y * c3;
        f = __half22float2(*reinterpret_cast<__half2*>(&u3.z)); a4 += f.x * c3; a5 += f.y * c3;
        f = __half22float2(*reinterpret_cast<__half2*>(&u3.w)); a6 += f.x * c3; a7 += f.y * c3;
    }
    for (; ed < e1; ed++) {
        int s0 = __ldg(&g_esrc[ed]);
        float c0 = __ldg(&g_inv_out[s0]);
        uint4 u0 = __ldg(reinterpret_cast<const uint4*>(&g_h16[(long)s0 * D + lane * 8]));
        float2 f;
        f = __half22float2(*reinterpret_cast<__half2*>(&u0.x)); a0 += f.x * c0; a1 += f.y * c0;
        f = __half22float2(*reinterpret_cast<__half2*>(&u0.y)); a2 += f.x * c0; a3 += f.y * c0;
        f = __half22float2(*reinterpret_cast<__half2*>(&u0.z)); a4 += f.x * c0; a5 += f.y * c0;
        f = __half22float2(*reinterpret_cast<__half2*>(&u0.w)); a6 += f.x * c0; a7 += f.y * c0;
    }
    float si = g_inv_in[node];
    uint32_t h0, l0, h1, l1, h2, l2, h3, l3;
    split_pair(a0 * si, a1 * si, h0, l0);
    split_pair(a2 * si, a3 * si, h1, l1);
    split_pair(a4 * si, a5 * si, h2, l2);
    split_pair(a6 * si, a7 * si, h3, l3);
    long off = (long)node * 512 + lane * 8;
    *reinterpret_cast<uint4*>(&g_A_hi[off]) = make_uint4(h0, h1, h2, h3);
    *reinterpret_cast<uint4*>(&g_A_lo[off]) = make_uint4(l0, l1, l2, l3);
}

// ---- split-bf16 HMMA GEMM with fused BN column stats (pre-split A) ----
#define ASTRIDE 40
__global__ void __launch_bounds__(256)
gemm_mma_kernel(int layer, const float* __restrict__ bvec,
                const float* __restrict__ blvec, int n) {
    __shared__ __nv_bfloat16 sAhi[128 * ASTRIDE];
    __shared__ __nv_bfloat16 sAlo[128 * ASTRIDE];
    __shared__ __nv_bfloat16 sBhi[128 * ASTRIDE];
    __shared__ __nv_bfloat16 sBlo[128 * ASTRIDE];
    __shared__ float s_sum[128];
    __shared__ float s_sq[128];

    int tid = threadIdx.x;
    int wid = tid >> 5, lane = tid & 31;
    int warp_m = wid >> 2;
    int warp_n = wid & 3;
    int rowBase = blockIdx.x * 128;
    int colBase = blockIdx.y * 128;

    if (tid < 128) { s_sum[tid] = 0.0f; s_sq[tid] = 0.0f; }

    uint32_t baseAhi = cvta_s(sAhi), baseAlo = cvta_s(sAlo);
    uint32_t baseBhi = cvta_s(sBhi), baseBlo = cvta_s(sBlo);

    const __nv_bfloat16* imgHi = g_Bimg_hi + (size_t)layer * 256 * 512;
    const __nv_bfloat16* imgLo = g_Bimg_lo + (size_t)layer * 256 * 512;

    float c[4][4][4];
#pragma unroll
    for (int i = 0; i < 4; i++)
#pragma unroll
        for (int j = 0; j < 4; j++)
#pragma unroll
            for (int q = 0; q < 4; q++) c[i][j][q] = 0.0f;

    int lrow = lane & 15;
    int lhalf = lane >> 4;

    for (int kt = 0; kt < 16; kt++) {
        // A tile: copy pre-split images (128 rows x 32 k, hi+lo)
#pragma unroll
        for (int i = 0; i < 4; i++) {
            int idx = tid + i * 256;
            int half = idx >> 9;
            int j = idx & 511;
            int row = j >> 2, q = j & 3;
            const __nv_bfloat16* srcp = (half ? g_A_lo : g_A_hi)
                + ((long)(rowBase + row) * 512 + kt * 32 + q * 8);
            uint4 val = *reinterpret_cast<const uint4*>(srcp);
            __nv_bfloat16* dstp = (half ? sAlo : sAhi) + row * ASTRIDE + q * 8;
            *reinterpret_cast<uint4*>(dstp) = val;
        }
        // B tile: copy pre-split images
#pragma unroll
        for (int i = 0; i < 4; i++) {
            int idx = tid + i * 256;
            int half = idx >> 9;
            int j = idx & 511;
            int nrow = j >> 2, q = j & 3;
            const __nv_bfloat16* srcp = (half ? imgLo : imgHi)
                + ((size_t)(colBase + nrow) * 512 + kt * 32 + q * 8);
            uint4 val = *reinterpret_cast<const uint4*>(srcp);
            __nv_bfloat16* dstp = (half ? sBlo : sBhi) + nrow * ASTRIDE + q * 8;
            *reinterpret_cast<uint4*>(dstp) = val;
        }
        __syncthreads();

#pragma unroll
        for (int ks = 0; ks < 2; ks++) {
            uint32_t ahi[4][4], alo[4][4];
#pragma unroll
            for (int mt = 0; mt < 4; mt++) {
                uint32_t off = (uint32_t)((warp_m * 64 + mt * 16 + lrow) * 80
                                          + ks * 32 + lhalf * 16);
                ldm_x4(ahi[mt][0], ahi[mt][1], ahi[mt][2], ahi[mt][3], baseAhi + off);
                ldm_x4(alo[mt][0], alo[mt][1], alo[mt][2], alo[mt][3], baseAlo + off);
            }
            uint32_t bhi[4][2], blo[4][2];
#pragma unroll
            for (int np = 0; np < 2; np++) {
                uint32_t off = (uint32_t)((warp_n * 32 + np * 16 + lrow) * 80
                                          + ks * 32 + lhalf * 16);
                uint32_t q0, q1, q2, q3;
                ldm_x4(q0, q1, q2, q3, baseBhi + off);
                bhi[np * 2 + 0][0] = q0; bhi[np * 2 + 0][1] = q2;
                bhi[np * 2 + 1][0] = q1; bhi[np * 2 + 1][1] = q3;
                ldm_x4(q0, q1, q2, q3, baseBlo + off);
                blo[np * 2 + 0][0] = q0; blo[np * 2 + 0][1] = q2;
                blo[np * 2 + 1][0] = q1; blo[np * 2 + 1][1] = q3;
            }
#pragma unroll
            for (int mt = 0; mt < 4; mt++)
#pragma unroll
                for (int nt = 0; nt < 4; nt++) {
                    mma_bf16(c[mt][nt], ahi[mt], bhi[nt][0], bhi[nt][1]);
                    mma_bf16(c[mt][nt], ahi[mt], blo[nt][0], blo[nt][1]);
                    mma_bf16(c[mt][nt], alo[mt], bhi[nt][0], bhi[nt][1]);
                }
        }
        __syncthreads();
    }

#pragma unroll
    for (int nt = 0; nt < 4; nt++) {
        int lc = warp_n * 32 + nt * 8 + (lane & 3) * 2;
        int col = colBase + lc;
        float bx = bvec[col] + blvec[col];
        float by = bvec[col + 1] + blvec[col + 1];
        float csx = 0.f, csy = 0.f, cqx = 0.f, cqy = 0.f;
#pragma unroll
        for (int mt = 0; mt < 4; mt++) {
            int r0 = rowBase + warp_m * 64 + mt * 16 + (lane >> 2);
            if (r0 < n) {
                float vx = c[mt][nt][0] + bx, vy = c[mt][nt][1] + by;
                *reinterpret_cast<float2*>(&g_outb[(long)r0 * D + col]) =
                    make_float2(vx, vy);
                csx += vx; csy += vy; cqx += vx * vx; cqy += vy * vy;
            }
            int r1 = r0 + 8;
            if (r1 < n) {
                float vx = c[mt][nt][2] + bx, vy = c[mt][nt][3] + by;
                *reinterpret_cast<float2*>(&g_outb[(long)r1 * D + col]) =
                    make_float2(vx, vy);
                csx += vx; csy += vy; cqx += vx * vx; cqy += vy * vy;
            }
        }
        atomicAdd(&s_sum[lc], csx);
        atomicAdd(&s_sum[lc + 1], csy);
        atomicAdd(&s_sq[lc], cqx);
        atomicAdd(&s_sq[lc + 1], cqy);
    }
    __syncthreads();
    if (tid < 128) {
        atomicAdd(&g_sum[colBase + tid], s_sum[tid]);
        atomicAdd(&g_sq[colBase + tid], s_sq[tid]);
    }
}

// ---- BN finalize ----
__global__ void bn_fin_kernel(int n) {
    int c = threadIdx.x;
    if (c < D) {
        float inv_n = 1.0f / (float)n;
        float mean = g_sum[c] * inv_n;
        float var = g_sq[c] * inv_n - mean * mean;
        g_mean[c] = mean;
        g_istd[c] = rsqrtf(var + BN_EPS);
    }
}

// ---- normalize + ReLU ----
// islast: write fp32 to dstp. else: write h16 image + h-half of A split images.
__global__ void norm_relu_kernel(const float* __restrict__ gamma,
                                 const float* __restrict__ beta,
                                 float* __restrict__ dstp, int n, int islast) {
    int total4 = n * (D / 4);
    const float4* o4 = reinterpret_cast<const float4*>(g_outb);
    float4* d4 = reinterpret_cast<float4*>(dstp);
    __half2* h2 = reinterpret_cast<__half2*>(g_h16);
    for (int i = blockIdx.x * blockDim.x + threadIdx.x; i < total4;
         i += gridDim.x * blockDim.x) {
        int c = (i * 4) & (D - 1);
        float4 o = o4[i];
        float4 g = *reinterpret_cast<const float4*>(&gamma[c]);
        float4 be = *reinterpret_cast<const float4*>(&beta[c]);
        float4 m = *reinterpret_cast<const float4*>(&g_mean[c]);
        float4 s = *reinterpret_cast<const float4*>(&g_istd[c]);
        float4 r;
        r.x = fmaxf(g.x * (o.x - m.x) * s.x + be.x, 0.0f);
        r.y = fmaxf(g.y * (o.y - m.y) * s.y + be.y, 0.0f);
        r.z = fmaxf(g.z * (o.z - m.z) * s.z + be.z, 0.0f);
        r.w = fmaxf(g.w * (o.w - m.w) * s.w + be.w, 0.0f);
        if (islast) {
            d4[i] = r;
        } else {
            h2[i * 2 + 0] = __floats2half2_rn(r.x, r.y);
            h2[i * 2 + 1] = __floats2half2_rn(r.z, r.w);
            int node = i >> 6;
            uint32_t h0, l0, h1, l1;
            split_pair(r.x, r.y, h0, l0);
            split_pair(r.z, r.w, h1, l1);
            long off = (long)node * 512 + 256 + c;
            *reinterpret_cast<uint2*>(&g_A_hi[off]) = make_uint2(h0, h1);
            *reinterpret_cast<uint2*>(&g_A_lo[off]) = make_uint2(l0, l1);
        }
    }
}

// ---- host launcher ----
extern "C" void kernel_launch(void* const* d_in, const int* in_sizes, int n_in,
                              void* d_out, int out_size) {
    const float* x     = (const float*)d_in[0];
    const float* W     = (const float*)d_in[1];
    const float* b     = (const float*)d_in[2];
    const float* Wl    = (const float*)d_in[3];
    const float* bl    = (const float*)d_in[4];
    const float* gamma = (const float*)d_in[5];
    const float* beta  = (const float*)d_in[6];
    const int*   src   = (const int*)d_in[7];
    const int*   dst   = (const int*)d_in[8];

    int n = in_sizes[0] / D;
    int e = in_sizes[7];
    int nl = in_sizes[1] / (D * D);

    const int T = 256;
    int nblk = (n + T - 1) / T;
    int sblk = (n + SCAN_CHUNK - 1) / SCAN_CHUNK;

    // degrees + CSR (once; graph static across layers)
    zero_deg_kernel<<<nblk, T>>>(n);
    deg_accum_kernel<<<1184, T>>>(src, dst, e);
    deg_fin_kernel<<<nblk, T>>>(n);
    scan1_kernel<<<sblk, 1024>>>(n);
    scan2_kernel<<<1, 32>>>(sblk, n);
    scan3_kernel<<<nblk, T>>>(n);
    bucket_kernel<<<1184, T>>>(src, dst, e);

    // weight prep + x images
    int preptasks = nl * 256 * 512;
    prep_B_kernel<<<(preptasks + T - 1) / T, T>>>(W, Wl, nl);
    xprep_kernel<<<1184, T>>>(x, n);

    int gatherb = (n * 32 + T - 1) / T;
    for (int l = 0; l < nl; l++) {
        zero_stats_kernel<<<1, T>>>();
        gather_kernel<<<gatherb, T>>>(n);
        dim3 gg((n + 127) / 128, 2);
        gemm_mma_kernel<<<gg, T>>>(l, b + l * D, bl + l * D, n);
        bn_fin_kernel<<<1, T>>>(n);
        norm_relu_kernel<<<1184, T>>>(gamma + l * D, beta + l * D,
                                      (float*)d_out, n, (l == nl - 1) ? 1 : 0);
    }
}

// round 11
// speedup vs baseline: 2.6420x; 1.0758x over previous
#include <cuda_runtime.h>
#include <cuda_bf16.h>
#include <cuda_fp16.h>
#include <cstdint>

#define D 256
#define MAXN 100000
#define NPAD (MAXN + 128)
#define MAXE 3200000
#define BN_EPS 1e-5f
#define LMAX 3
#define SCAN_CHUNK 4096

// ---- scratch (static device globals; no allocation allowed) ----
__device__ __align__(128) __half g_h16[MAXN * D];          // fp16 image for gather
__device__ __align__(128) float g_outb[MAXN * D];          // pre-BN output
// A operand split-bf16 images: [node][k=0..511] (k<256: agg, k>=256: h)
__device__ __align__(128) __nv_bfloat16 g_A_hi[NPAD * 512];
__device__ __align__(128) __nv_bfloat16 g_A_lo[NPAD * 512];
__device__ float g_inv_out[MAXN];
__device__ float g_inv_in[MAXN];
__device__ int   g_degi_out[MAXN];
__device__ int   g_degi_in[MAXN];
__device__ int   g_rowp[MAXN + 1];
__device__ int   g_cursor[MAXN];
__device__ int   g_esrc[MAXE];
__device__ int   g_bsum[128];
__device__ int   g_boff[128];
__device__ float g_sum[D];
__device__ float g_sq[D];
__device__ float g_mean[D];
__device__ float g_istd[D];
// Weight images: B^T layout [L][n=256][k=512] bf16, hi and lo halves.
__device__ __align__(128) __nv_bfloat16 g_Bimg_hi[LMAX * 256 * 512];
__device__ __align__(128) __nv_bfloat16 g_Bimg_lo[LMAX * 256 * 512];

// ---- helpers ----
__device__ __forceinline__ uint32_t cvta_s(const void* p) {
    uint32_t a;
    asm("{ .reg .u64 t; cvta.to.shared.u64 t, %1; cvt.u32.u64 %0, t; }"
        : "=r"(a) : "l"(p));
    return a;
}
__device__ __forceinline__ void ldm_x4(uint32_t& r0, uint32_t& r1,
                                       uint32_t& r2, uint32_t& r3, uint32_t a) {
    asm volatile("ldmatrix.sync.aligned.m8n8.x4.shared.b16 {%0,%1,%2,%3}, [%4];"
                 : "=r"(r0), "=r"(r1), "=r"(r2), "=r"(r3) : "r"(a));
}
__device__ __forceinline__ void mma_bf16(float* c, const uint32_t* a,
                                         uint32_t b0, uint32_t b1) {
    asm volatile(
        "mma.sync.aligned.m16n8k16.row.col.f32.bf16.bf16.f32 "
        "{%0,%1,%2,%3}, {%4,%5,%6,%7}, {%8,%9}, {%0,%1,%2,%3};"
        : "+f"(c[0]), "+f"(c[1]), "+f"(c[2]), "+f"(c[3])
        : "r"(a[0]), "r"(a[1]), "r"(a[2]), "r"(a[3]), "r"(b0), "r"(b1));
}
__device__ __forceinline__ void cp16(uint32_t saddr, const void* g) {
    asm volatile("cp.async.cg.shared.global [%0], [%1], 16;"
                 :: "r"(saddr), "l"(g) : "memory");
}
__device__ __forceinline__ uint32_t pack_bf2(__nv_bfloat16 a, __nv_bfloat16 b) {
    return (uint32_t)__bfloat16_as_ushort(a) | ((uint32_t)__bfloat16_as_ushort(b) << 16);
}
__device__ __forceinline__ void split_pair(float x, float y, uint32_t& hi, uint32_t& lo) {
    __nv_bfloat16 hx = __float2bfloat16(x);
    __nv_bfloat16 hy = __float2bfloat16(y);
    float rx = x - __bfloat162float(hx);
    float ry = y - __bfloat162float(hy);
    hi = pack_bf2(hx, hy);
    lo = pack_bf2(__float2bfloat16(rx), __float2bfloat16(ry));
}

// ---- degree / CSR build ----
__global__ void zero_deg_kernel(int n) {
    for (int i = blockIdx.x * blockDim.x + threadIdx.x; i < n;
         i += gridDim.x * blockDim.x) {
        g_degi_out[i] = 0;
        g_degi_in[i] = 0;
    }
}
__global__ void deg_accum_kernel(const int* __restrict__ src,
                                 const int* __restrict__ dst, int e) {
    for (int i = blockIdx.x * blockDim.x + threadIdx.x; i < e;
         i += gridDim.x * blockDim.x) {
        atomicAdd(&g_degi_out[src[i]], 1);
        atomicAdd(&g_degi_in[dst[i]], 1);
    }
}
__global__ void deg_fin_kernel(int n) {
    for (int i = blockIdx.x * blockDim.x + threadIdx.x; i < n;
         i += gridDim.x * blockDim.x) {
        g_inv_out[i] = rsqrtf(fmaxf((float)g_degi_out[i], 1.0f));
        g_inv_in[i]  = rsqrtf(fmaxf((float)g_degi_in[i], 1.0f));
    }
}
__global__ void __launch_bounds__(1024)
scan1_kernel(int n) {
    __shared__ int wsum[32];
    int t = threadIdx.x;
    int lane = t & 31, w = t >> 5;
    int base = blockIdx.x * SCAN_CHUNK + t * 4;
    int v0 = (base + 0 < n) ? g_degi_in[base + 0] : 0;
    int v1 = (base + 1 < n) ? g_degi_in[base + 1] : 0;
    int v2 = (base + 2 < n) ? g_degi_in[base + 2] : 0;
    int v3 = (base + 3 < n) ? g_degi_in[base + 3] : 0;
    int s = v0 + v1 + v2 + v3;
    int inc = s;
#pragma unroll
    for (int o = 1; o < 32; o <<= 1) {
        int u = __shfl_up_sync(0xFFFFFFFFu, inc, o);
        if (lane >= o) inc += u;
    }
    if (lane == 31) wsum[w] = inc;
    __syncthreads();
    if (w == 0) {
        int ws = wsum[lane];
#pragma unroll
        for (int o = 1; o < 32; o <<= 1) {
            int u = __shfl_up_sync(0xFFFFFFFFu, ws, o);
            if (lane >= o) ws += u;
        }
        wsum[lane] = ws;
    }
    __syncthreads();
    int excl = inc - s + (w > 0 ? wsum[w - 1] : 0);
    if (base + 0 < n) g_rowp[base + 0] = excl;
    if (base + 1 < n) g_rowp[base + 1] = excl + v0;
    if (base + 2 < n) g_rowp[base + 2] = excl + v0 + v1;
    if (base + 3 < n) g_rowp[base + 3] = excl + v0 + v1 + v2;
    if (t == 1023) g_bsum[blockIdx.x] = wsum[31];
}
__global__ void scan2_kernel(int nblk, int n) {
    if (threadIdx.x == 0) {
        int run = 0;
        for (int b = 0; b < nblk; b++) {
            g_boff[b] = run;
            run += g_bsum[b];
        }
        g_rowp[n] = run;
    }
}
__global__ void scan3_kernel(int n) {
    for (int i = blockIdx.x * blockDim.x + threadIdx.x; i < n;
         i += gridDim.x * blockDim.x) {
        int v = g_rowp[i] + g_boff[i / SCAN_CHUNK];
        g_rowp[i] = v;
        g_cursor[i] = v;
    }
}
__global__ void bucket_kernel(const int* __restrict__ src,
                              const int* __restrict__ dst, int e) {
    for (int i = blockIdx.x * blockDim.x + threadIdx.x; i < e;
         i += gridDim.x * blockDim.x) {
        int pos = atomicAdd(&g_cursor[dst[i]], 1);
        g_esrc[pos] = src[i];
    }
}

// ---- weight prep ----
__global__ void prep_B_kernel(const float* __restrict__ W,
                              const float* __restrict__ Wl, int nl) {
    int idx = blockIdx.x * blockDim.x + threadIdx.x;
    int total = nl * 256 * 512;
    if (idx >= total) return;
    int k = idx & 511;
    int nn = (idx >> 9) & 255;
    int l = idx >> 17;
    float w;
    if (k < 256) {
        w = W[((size_t)l * D + k) * D + nn];
    } else {
        w = Wl[((size_t)l * D + (k - 256)) * D + nn];
        if ((k - 256) == nn) w += 1.0f;
    }
    __nv_bfloat16 hi = __float2bfloat16(w);
    __nv_bfloat16 lo = __float2bfloat16(w - __bfloat162float(hi));
    g_Bimg_hi[idx] = hi;
    g_Bimg_lo[idx] = lo;
}

__global__ void zero_stats_kernel() {
    if (threadIdx.x < D) {
        g_sum[threadIdx.x] = 0.0f;
        g_sq[threadIdx.x] = 0.0f;
    }
}

// ---- x prep (once): fp16 image + h-half of A split images ----
__global__ void xprep_kernel(const float* __restrict__ x, int n) {
    int total4 = n * (D / 4);
    const float4* x4 = reinterpret_cast<const float4*>(x);
    __half2* o2 = reinterpret_cast<__half2*>(g_h16);
    for (int i = blockIdx.x * blockDim.x + threadIdx.x; i < total4;
         i += gridDim.x * blockDim.x) {
        float4 v = x4[i];
        o2[i * 2 + 0] = __floats2half2_rn(v.x, v.y);
        o2[i * 2 + 1] = __floats2half2_rn(v.z, v.w);
        int node = i >> 6;
        int c = (i & 63) * 4;
        uint32_t h0, l0, h1, l1;
        split_pair(v.x, v.y, h0, l0);
        split_pair(v.z, v.w, h1, l1);
        long off = (long)node * 512 + 256 + c;
        *reinterpret_cast<uint2*>(&g_A_hi[off]) = make_uint2(h0, h1);
        *reinterpret_cast<uint2*>(&g_A_lo[off]) = make_uint2(l0, l1);
    }
}

// ---- gather aggregate (fp16 source, fp32 accum) -> split-bf16 agg image ----
__global__ void __launch_bounds__(256)
gather_kernel(int n) {
    int node = (blockIdx.x * blockDim.x + threadIdx.x) >> 5;
    if (node >= n) return;
    int lane = threadIdx.x & 31;
    int e0 = __ldg(&g_rowp[node]);
    int e1 = __ldg(&g_rowp[node + 1]);
    float a0 = 0.f, a1 = 0.f, a2 = 0.f, a3 = 0.f;
    float a4 = 0.f, a5 = 0.f, a6 = 0.f, a7 = 0.f;
    int ed = e0;
    for (; ed + 4 <= e1; ed += 4) {
        int s0 = __ldg(&g_esrc[ed]);
        int s1 = __ldg(&g_esrc[ed + 1]);
        int s2 = __ldg(&g_esrc[ed + 2]);
        int s3 = __ldg(&g_esrc[ed + 3]);
        float c0 = __ldg(&g_inv_out[s0]);
        float c1 = __ldg(&g_inv_out[s1]);
        float c2 = __ldg(&g_inv_out[s2]);
        float c3 = __ldg(&g_inv_out[s3]);
        uint4 u0 = __ldg(reinterpret_cast<const uint4*>(&g_h16[(long)s0 * D + lane * 8]));
        uint4 u1 = __ldg(reinterpret_cast<const uint4*>(&g_h16[(long)s1 * D + lane * 8]));
        uint4 u2 = __ldg(reinterpret_cast<const uint4*>(&g_h16[(long)s2 * D + lane * 8]));
        uint4 u3 = __ldg(reinterpret_cast<const uint4*>(&g_h16[(long)s3 * D + lane * 8]));
        float2 f;
        f = __half22float2(*reinterpret_cast<__half2*>(&u0.x)); a0 += f.x * c0; a1 += f.y * c0;
        f = __half22float2(*reinterpret_cast<__half2*>(&u0.y)); a2 += f.x * c0; a3 += f.y * c0;
        f = __half22float2(*reinterpret_cast<__half2*>(&u0.z)); a4 += f.x * c0; a5 += f.y * c0;
        f = __half22float2(*reinterpret_cast<__half2*>(&u0.w)); a6 += f.x * c0; a7 += f.y * c0;
        f = __half22float2(*reinterpret_cast<__half2*>(&u1.x)); a0 += f.x * c1; a1 += f.y * c1;
        f = __half22float2(*reinterpret_cast<__half2*>(&u1.y)); a2 += f.x * c1; a3 += f.y * c1;
        f = __half22float2(*reinterpret_cast<__half2*>(&u1.z)); a4 += f.x * c1; a5 += f.y * c1;
        f = __half22float2(*reinterpret_cast<__half2*>(&u1.w)); a6 += f.x * c1; a7 += f.y * c1;
        f = __half22float2(*reinterpret_cast<__half2*>(&u2.x)); a0 += f.x * c2; a1 += f.y * c2;
        f = __half22float2(*reinterpret_cast<__half2*>(&u2.y)); a2 += f.x * c2; a3 += f.y * c2;
        f = __half22float2(*reinterpret_cast<__half2*>(&u2.z)); a4 += f.x * c2; a5 += f.y * c2;
        f = __half22float2(*reinterpret_cast<__half2*>(&u2.w)); a6 += f.x * c2; a7 += f.y * c2;
        f = __half22float2(*reinterpret_cast<__half2*>(&u3.x)); a0 += f.x * c3; a1 += f.y * c3;
        f = __half22float2(*reinterpret_cast<__half2*>(&u3.y)); a2 += f.x * c3; a3 += f.y * c3;
        f = __half22float2(*reinterpret_cast<__half2*>(&u3.z)); a4 += f.x * c3; a5 += f.y * c3;
        f = __half22float2(*reinterpret_cast<__half2*>(&u3.w)); a6 += f.x * c3; a7 += f.y * c3;
    }
    for (; ed < e1; ed++) {
        int s0 = __ldg(&g_esrc[ed]);
        float c0 = __ldg(&g_inv_out[s0]);
        uint4 u0 = __ldg(reinterpret_cast<const uint4*>(&g_h16[(long)s0 * D + lane * 8]));
        float2 f;
        f = __half22float2(*reinterpret_cast<__half2*>(&u0.x)); a0 += f.x * c0; a1 += f.y * c0;
        f = __half22float2(*reinterpret_cast<__half2*>(&u0.y)); a2 += f.x * c0; a3 += f.y * c0;
        f = __half22float2(*reinterpret_cast<__half2*>(&u0.z)); a4 += f.x * c0; a5 += f.y * c0;
        f = __half22float2(*reinterpret_cast<__half2*>(&u0.w)); a6 += f.x * c0; a7 += f.y * c0;
    }
    float si = g_inv_in[node];
    uint32_t h0, l0, h1, l1, h2, l2, h3, l3;
    split_pair(a0 * si, a1 * si, h0, l0);
    split_pair(a2 * si, a3 * si, h1, l1);
    split_pair(a4 * si, a5 * si, h2, l2);
    split_pair(a6 * si, a7 * si, h3, l3);
    long off = (long)node * 512 + lane * 8;
    *reinterpret_cast<uint4*>(&g_A_hi[off]) = make_uint4(h0, h1, h2, h3);
    *reinterpret_cast<uint4*>(&g_A_lo[off]) = make_uint4(l0, l1, l2, l3);
}

// ---- split-bf16 HMMA GEMM: cp.async double-buffered, fused BN stats ----
#define ASTRIDE 40
#define TILE_B 10240                       // 128 * ASTRIDE * 2 bytes
#define GEMM_SMEM (8 * TILE_B)             // 2 stages x (Ahi,Alo,Bhi,Blo)
__global__ void __launch_bounds__(256)
gemm_mma_kernel(int layer, const float* __restrict__ bvec,
                const float* __restrict__ blvec, int n) {
    extern __shared__ char smem[];
    __shared__ float s_sum[128];
    __shared__ float s_sq[128];

    int tid = threadIdx.x;
    int wid = tid >> 5, lane = tid & 31;
    int warp_m = wid >> 2;
    int warp_n = wid & 3;
    int rowBase = blockIdx.x * 128;
    int colBase = blockIdx.y * 128;

    if (tid < 128) { s_sum[tid] = 0.0f; s_sq[tid] = 0.0f; }

    uint32_t sb = cvta_s(smem);
    // stage s: Ahi at s*4*TILE_B, Alo +TILE_B, Bhi +2*TILE_B, Blo +3*TILE_B
    const __nv_bfloat16* imgHi = g_Bimg_hi + (size_t)layer * 256 * 512;
    const __nv_bfloat16* imgLo = g_Bimg_lo + (size_t)layer * 256 * 512;

    // per-thread load slots: 4 chunks A (hi+lo interleaved by idx) + 4 chunks B
    // idx = tid + i*256, i in 0..3 -> 1024 slots covering {half, row, q}
    auto issue_tile = [&](int kt, int stage) {
        uint32_t sbase = sb + stage * 4 * TILE_B;
#pragma unroll
        for (int i = 0; i < 4; i++) {
            int idx = tid + i * 256;
            int half = idx >> 9;
            int j = idx & 511;
            int row = j >> 2, q = j & 3;
            const __nv_bfloat16* srcp = (half ? g_A_lo : g_A_hi)
                + ((long)(rowBase + row) * 512 + kt * 32 + q * 8);
            cp16(sbase + half * TILE_B + row * 80 + q * 16, srcp);
        }
#pragma unroll
        for (int i = 0; i < 4; i++) {
            int idx = tid + i * 256;
            int half = idx >> 9;
            int j = idx & 511;
            int nrow = j >> 2, q = j & 3;
            const __nv_bfloat16* srcp = (half ? imgLo : imgHi)
                + ((size_t)(colBase + nrow) * 512 + kt * 32 + q * 8);
            cp16(sbase + (2 + half) * TILE_B + nrow * 80 + q * 16, srcp);
        }
        asm volatile("cp.async.commit_group;" ::: "memory");
    };

    float c[4][4][4];
#pragma unroll
    for (int i = 0; i < 4; i++)
#pragma unroll
        for (int j = 0; j < 4; j++)
#pragma unroll
            for (int q = 0; q < 4; q++) c[i][j][q] = 0.0f;

    int lrow = lane & 15;
    int lhalf = lane >> 4;

    issue_tile(0, 0);

    for (int kt = 0; kt < 16; kt++) {
        if (kt < 15) {
            issue_tile(kt + 1, (kt + 1) & 1);
            asm volatile("cp.async.wait_group 1;" ::: "memory");
        } else {
            asm volatile("cp.async.wait_group 0;" ::: "memory");
        }
        __syncthreads();

        uint32_t sbase = sb + (kt & 1) * 4 * TILE_B;
        uint32_t bAhi = sbase, bAlo = sbase + TILE_B;
        uint32_t bBhi = sbase + 2 * TILE_B, bBlo = sbase + 3 * TILE_B;

#pragma unroll
        for (int ks = 0; ks < 2; ks++) {
            uint32_t ahi[4][4], alo[4][4];
#pragma unroll
            for (int mt = 0; mt < 4; mt++) {
                uint32_t off = (uint32_t)((warp_m * 64 + mt * 16 + lrow) * 80
                                          + ks * 32 + lhalf * 16);
                ldm_x4(ahi[mt][0], ahi[mt][1], ahi[mt][2], ahi[mt][3], bAhi + off);
                ldm_x4(alo[mt][0], alo[mt][1], alo[mt][2], alo[mt][3], bAlo + off);
            }
            uint32_t bhi[4][2], blo[4][2];
#pragma unroll
            for (int np = 0; np < 2; np++) {
                uint32_t off = (uint32_t)((warp_n * 32 + np * 16 + lrow) * 80
                                          + ks * 32 + lhalf * 16);
                uint32_t q0, q1, q2, q3;
                ldm_x4(q0, q1, q2, q3, bBhi + off);
                bhi[np * 2 + 0][0] = q0; bhi[np * 2 + 0][1] = q2;
                bhi[np * 2 + 1][0] = q1; bhi[np * 2 + 1][1] = q3;
                ldm_x4(q0, q1, q2, q3, bBlo + off);
                blo[np * 2 + 0][0] = q0; blo[np * 2 + 0][1] = q2;
                blo[np * 2 + 1][0] = q1; blo[np * 2 + 1][1] = q3;
            }
#pragma unroll
            for (int mt = 0; mt < 4; mt++)
#pragma unroll
                for (int nt = 0; nt < 4; nt++) {
                    mma_bf16(c[mt][nt], ahi[mt], bhi[nt][0], bhi[nt][1]);
                    mma_bf16(c[mt][nt], ahi[mt], blo[nt][0], blo[nt][1]);
                    mma_bf16(c[mt][nt], alo[mt], bhi[nt][0], bhi[nt][1]);
                }
        }
        __syncthreads();
    }

    // ---- epilogue: + (b + bl), write g_outb, fused BN column stats ----
#pragma unroll
    for (int nt = 0; nt < 4; nt++) {
        int lc = warp_n * 32 + nt * 8 + (lane & 3) * 2;
        int col = colBase + lc;
        float bx = bvec[col] + blvec[col];
        float by = bvec[col + 1] + blvec[col + 1];
        float csx = 0.f, csy = 0.f, cqx = 0.f, cqy = 0.f;
#pragma unroll
        for (int mt = 0; mt < 4; mt++) {
            int r0 = rowBase + warp_m * 64 + mt * 16 + (lane >> 2);
            if (r0 < n) {
                float vx = c[mt][nt][0] + bx, vy = c[mt][nt][1] + by;
                *reinterpret_cast<float2*>(&g_outb[(long)r0 * D + col]) =
                    make_float2(vx, vy);
                csx += vx; csy += vy; cqx += vx * vx; cqy += vy * vy;
            }
            int r1 = r0 + 8;
            if (r1 < n) {
                float vx = c[mt][nt][2] + bx, vy = c[mt][nt][3] + by;
                *reinterpret_cast<float2*>(&g_outb[(long)r1 * D + col]) =
                    make_float2(vx, vy);
                csx += vx; csy += vy; cqx += vx * vx; cqy += vy * vy;
            }
        }
        atomicAdd(&s_sum[lc], csx);
        atomicAdd(&s_sum[lc + 1], csy);
        atomicAdd(&s_sq[lc], cqx);
        atomicAdd(&s_sq[lc + 1], cqy);
    }
    __syncthreads();
    if (tid < 128) {
        atomicAdd(&g_sum[colBase + tid], s_sum[tid]);
        atomicAdd(&g_sq[colBase + tid], s_sq[tid]);
    }
}

// ---- BN finalize ----
__global__ void bn_fin_kernel(int n) {
    int c = threadIdx.x;
    if (c < D) {
        float inv_n = 1.0f / (float)n;
        float mean = g_sum[c] * inv_n;
        float var = g_sq[c] * inv_n - mean * mean;
        g_mean[c] = mean;
        g_istd[c] = rsqrtf(var + BN_EPS);
    }
}

// ---- normalize + ReLU ----
__global__ void norm_relu_kernel(const float* __restrict__ gamma,
                                 const float* __restrict__ beta,
                                 float* __restrict__ dstp, int n, int islast) {
    int total4 = n * (D / 4);
    const float4* o4 = reinterpret_cast<const float4*>(g_outb);
    float4* d4 = reinterpret_cast<float4*>(dstp);
    __half2* h2 = reinterpret_cast<__half2*>(g_h16);
    for (int i = blockIdx.x * blockDim.x + threadIdx.x; i < total4;
         i += gridDim.x * blockDim.x) {
        int c = (i * 4) & (D - 1);
        float4 o = o4[i];
        float4 g = *reinterpret_cast<const float4*>(&gamma[c]);
        float4 be = *reinterpret_cast<const float4*>(&beta[c]);
        float4 m = *reinterpret_cast<const float4*>(&g_mean[c]);
        float4 s = *reinterpret_cast<const float4*>(&g_istd[c]);
        float4 r;
        r.x = fmaxf(g.x * (o.x - m.x) * s.x + be.x, 0.0f);
        r.y = fmaxf(g.y * (o.y - m.y) * s.y + be.y, 0.0f);
        r.z = fmaxf(g.z * (o.z - m.z) * s.z + be.z, 0.0f);
        r.w = fmaxf(g.w * (o.w - m.w) * s.w + be.w, 0.0f);
        if (islast) {
            d4[i] = r;
        } else {
            h2[i * 2 + 0] = __floats2half2_rn(r.x, r.y);
            h2[i * 2 + 1] = __floats2half2_rn(r.z, r.w);
            int node = i >> 6;
            uint32_t h0, l0, h1, l1;
            split_pair(r.x, r.y, h0, l0);
            split_pair(r.z, r.w, h1, l1);
            long off = (long)node * 512 + 256 + c;
            *reinterpret_cast<uint2*>(&g_A_hi[off]) = make_uint2(h0, h1);
            *reinterpret_cast<uint2*>(&g_A_lo[off]) = make_uint2(l0, l1);
        }
    }
}

// ---- host launcher ----
extern "C" void kernel_launch(void* const* d_in, const int* in_sizes, int n_in,
                              void* d_out, int out_size) {
    const float* x     = (const float*)d_in[0];
    const float* W     = (const float*)d_in[1];
    const float* b     = (const float*)d_in[2];
    const float* Wl    = (const float*)d_in[3];
    const float* bl    = (const float*)d_in[4];
    const float* gamma = (const float*)d_in[5];
    const float* beta  = (const float*)d_in[6];
    const int*   src   = (const int*)d_in[7];
    const int*   dst   = (const int*)d_in[8];

    int n = in_sizes[0] / D;
    int e = in_sizes[7];
    int nl = in_sizes[1] / (D * D);

    const int T = 256;
    int nblk = (n + T - 1) / T;
    int sblk = (n + SCAN_CHUNK - 1) / SCAN_CHUNK;

    cudaFuncSetAttribute(gemm_mma_kernel,
                         cudaFuncAttributeMaxDynamicSharedMemorySize, GEMM_SMEM);

    // degrees + CSR (once; graph static across layers)
    zero_deg_kernel<<<nblk, T>>>(n);
    deg_accum_kernel<<<1184, T>>>(src, dst, e);
    deg_fin_kernel<<<nblk, T>>>(n);
    scan1_kernel<<<sblk, 1024>>>(n);
    scan2_kernel<<<1, 32>>>(sblk, n);
    scan3_kernel<<<nblk, T>>>(n);
    bucket_kernel<<<1184, T>>>(src, dst, e);

    // weight prep + x images
    int preptasks = nl * 256 * 512;
    prep_B_kernel<<<(preptasks + T - 1) / T, T>>>(W, Wl, nl);
    xprep_kernel<<<1184, T>>>(x, n);

    int gatherb = (n * 32 + T - 1) / T;
    for (int l = 0; l < nl; l++) {
        zero_stats_kernel<<<1, T>>>();
        gather_kernel<<<gatherb, T>>>(n);
        dim3 gg((n + 127) / 128, 2);
        gemm_mma_kernel<<<gg, T, GEMM_SMEM>>>(l, b + l * D, bl + l * D, n);
        bn_fin_kernel<<<1, T>>>(n);
        norm_relu_kernel<<<1184, T>>>(gamma + l * D, beta + l * D,
                                      (float*)d_out, n, (l == nl - 1) ? 1 : 0);
    }
}